// round 3
// baseline (speedup 1.0000x reference)
#include <cuda_runtime.h>
#include <math.h>

#define BS   8
#define LSEQ 8192
#define D    128
#define H    128
#define DFF  512
#define NTOK (BS * LSEQ)   // 65536
#define CL   512
#define NCH  (LSEQ / CL)   // 16

// ---------------- device scratch (static; no runtime allocation) ----------------
__device__ __align__(16) float g_scal[BS][6];     // s1,b1,g1,s2,b2,g2 per batch
__device__ __align__(16) float g_loga[H];
__device__ __align__(16) float g_at[(size_t)NTOK * H];
__device__ __align__(16) float g_bt[(size_t)NTOK * H];
__device__ __align__(16) float g_hf[(size_t)NTOK * H];
__device__ __align__(16) float g_hb[(size_t)NTOK * H];
__device__ __align__(16) float g_x1[(size_t)NTOK * D];
__device__ __align__(16) float g_A [BS * NCH * H];
__device__ __align__(16) float g_Bf[BS * NCH * H];
__device__ __align__(16) float g_Bb[BS * NCH * H];
__device__ __align__(16) float g_cf[BS * NCH * H];
__device__ __align__(16) float g_cb[BS * NCH * H];

// ---------------- helpers ----------------
__device__ __forceinline__ float warp_sum(float v) {
    v += __shfl_xor_sync(0xffffffffu, v, 16);
    v += __shfl_xor_sync(0xffffffffu, v, 8);
    v += __shfl_xor_sync(0xffffffffu, v, 4);
    v += __shfl_xor_sync(0xffffffffu, v, 2);
    v += __shfl_xor_sync(0xffffffffu, v, 1);
    return v;
}

__device__ __forceinline__ float sigmoidf_(float v) {
    return 1.f / (1.f + expf(-v));
}

__device__ __forceinline__ float geluf_(float v) {
    // jax.nn.gelu default (approximate=True, tanh form)
    float v3 = v * v * v;
    return 0.5f * v * (1.f + tanhf(0.7978845608028654f * (v + 0.044715f * v3)));
}

// Load a 128x128 fp32 tile (row stride ldg floats) into smem [128][128]; 512 threads.
__device__ __forceinline__ void load_w128(float* sW, const float* __restrict__ g,
                                          int ldg, int tid) {
#pragma unroll
    for (int i = 0; i < 8; ++i) {
        int m = tid + i * 512;     // float4 index, 0..4095
        int k = m >> 5;            // row
        int j = m & 31;            // float4 within row
        reinterpret_cast<float4*>(sW)[m] =
            *reinterpret_cast<const float4*>(g + (size_t)k * ldg + j * 4);
    }
}

// C(64x128) += A(64x128 smem) * W(128x128 smem). 512 threads: trow=tid>>5 (16), tcol=tid&31 (32).
__device__ __forceinline__ void gemm_tile(const float* __restrict__ sA,
                                          const float* __restrict__ sW,
                                          float acc[4][4], int trow, int tcol) {
    const float* a0 = sA + (trow * 4 + 0) * 128;
    const float* a1 = sA + (trow * 4 + 1) * 128;
    const float* a2 = sA + (trow * 4 + 2) * 128;
    const float* a3 = sA + (trow * 4 + 3) * 128;
#pragma unroll 8
    for (int k = 0; k < 128; ++k) {
        float4 bv = reinterpret_cast<const float4*>(sW + k * 128)[tcol];
        float v0 = a0[k], v1 = a1[k], v2 = a2[k], v3 = a3[k];
        acc[0][0] = fmaf(v0, bv.x, acc[0][0]);
        acc[0][1] = fmaf(v0, bv.y, acc[0][1]);
        acc[0][2] = fmaf(v0, bv.z, acc[0][2]);
        acc[0][3] = fmaf(v0, bv.w, acc[0][3]);
        acc[1][0] = fmaf(v1, bv.x, acc[1][0]);
        acc[1][1] = fmaf(v1, bv.y, acc[1][1]);
        acc[1][2] = fmaf(v1, bv.z, acc[1][2]);
        acc[1][3] = fmaf(v1, bv.w, acc[1][3]);
        acc[2][0] = fmaf(v2, bv.x, acc[2][0]);
        acc[2][1] = fmaf(v2, bv.y, acc[2][1]);
        acc[2][2] = fmaf(v2, bv.z, acc[2][2]);
        acc[2][3] = fmaf(v2, bv.w, acc[2][3]);
        acc[3][0] = fmaf(v3, bv.x, acc[3][0]);
        acc[3][1] = fmaf(v3, bv.y, acc[3][1]);
        acc[3][2] = fmaf(v3, bv.z, acc[3][2]);
        acc[3][3] = fmaf(v3, bv.w, acc[3][3]);
    }
}

#define ZERO44(a) do { _Pragma("unroll") for (int _i=0;_i<4;++_i) { _Pragma("unroll") for (int _j=0;_j<4;++_j) (a)[_i][_j]=0.f; } } while(0)

// ---------------- K0: per-batch conditioning scalars + log(a) ----------------
__global__ void k_scal(const float* __restrict__ c,
                       const float* sw1, const float* sb1,
                       const float* bw1, const float* bb1,
                       const float* gw1, const float* gb1,
                       const float* sw2, const float* sb2,
                       const float* bw2, const float* bb2,
                       const float* gw2, const float* gb2,
                       const float* __restrict__ a) {
    int tid = threadIdx.x;
    if (tid < 48) {
        const float* ws[6] = {sw1, bw1, gw1, sw2, bw2, gw2};
        const float* bs[6] = {sb1, bb1, gb1, sb2, bb2, gb2};
        int b = tid / 6, j = tid % 6;
        float s = bs[j][0];
        const float* cp = c + b * 128;
        for (int k = 0; k < 128; ++k) s = fmaf(cp[k], ws[j][k], s);
        g_scal[b][j] = s;
    }
    int i = tid - 64;
    if (i >= 0 && i < H) g_loga[i] = logf(a[i]);
}

// ---------------- K1: x -> (at, bt)  [2 LNs + 3 GEMMs fused] ----------------
__global__ __launch_bounds__(512) void k_front(
    const float* __restrict__ x, const float* __restrict__ Win,
    const float* __restrict__ inb, const float* __restrict__ pos,
    const float* __restrict__ Wi, const float* __restrict__ bi,
    const float* __restrict__ Wr, const float* __restrict__ br) {
    extern __shared__ float sm[];
    float* sA = sm;             // 64x128 ln2
    float* sU = sm + 8192;      // 64x128 u
    float* sW = sm + 16384;     // 128x128 weights
    int tid = threadIdx.x;
    int lane = tid & 31, wid = tid >> 5;
    int n0 = blockIdx.x * 64;
    int b  = n0 >> 13;
    int l0 = n0 & (LSEQ - 1);
    float s1p = 1.f + g_scal[b][0];
    float b1s = g_scal[b][1];

    // double LayerNorm with conditioning, one token per warp per iter
#pragma unroll
    for (int it = 0; it < 4; ++it) {
        int row = wid * 4 + it;
        const float* xp = x + (size_t)(n0 + row) * D;
        float v0 = xp[lane], v1 = xp[lane + 32], v2 = xp[lane + 64], v3 = xp[lane + 96];
        float m = warp_sum(v0 + v1 + v2 + v3) * (1.f / 128.f);
        float d0 = v0 - m, d1 = v1 - m, d2 = v2 - m, d3 = v3 - m;
        float ss = warp_sum(d0*d0 + d1*d1 + d2*d2 + d3*d3);
        float rs = rsqrtf(ss * (1.f / 128.f) + 1e-6f);
        float h0 = fmaf(s1p, d0 * rs, b1s), h1 = fmaf(s1p, d1 * rs, b1s);
        float h2 = fmaf(s1p, d2 * rs, b1s), h3 = fmaf(s1p, d3 * rs, b1s);
        float m2 = warp_sum(h0 + h1 + h2 + h3) * (1.f / 128.f);
        float e0 = h0 - m2, e1 = h1 - m2, e2 = h2 - m2, e3 = h3 - m2;
        float ss2 = warp_sum(e0*e0 + e1*e1 + e2*e2 + e3*e3);
        float rs2 = rsqrtf(ss2 * (1.f / 128.f) + 1e-6f);
        float* ap = sA + row * 128;
        ap[lane]      = e0 * rs2;
        ap[lane + 32] = e1 * rs2;
        ap[lane + 64] = e2 * rs2;
        ap[lane + 96] = e3 * rs2;
    }
    load_w128(sW, Win, 128, tid);
    __syncthreads();

    int tcol = lane, trow = wid;
    float acc[4][4];
    ZERO44(acc);
    gemm_tile(sA, sW, acc, trow, tcol);

    // u = ln2 @ Win + in_b + pos
    float4 ib4 = reinterpret_cast<const float4*>(inb)[tcol];
#pragma unroll
    for (int i = 0; i < 4; ++i) {
        int row = trow * 4 + i;
        float4 pv = reinterpret_cast<const float4*>(pos + (size_t)(l0 + row) * H)[tcol];
        float4 uv;
        uv.x = acc[i][0] + ib4.x + pv.x;
        uv.y = acc[i][1] + ib4.y + pv.y;
        uv.z = acc[i][2] + ib4.z + pv.z;
        uv.w = acc[i][3] + ib4.w + pv.w;
        reinterpret_cast<float4*>(sU + row * 128)[tcol] = uv;
    }
    __syncthreads();

    load_w128(sW, Wi, 128, tid);
    __syncthreads();
    ZERO44(acc);
    gemm_tile(sU, sW, acc, trow, tcol);
    float gi[4][4];
    {
        float4 bi4 = reinterpret_cast<const float4*>(bi)[tcol];
#pragma unroll
        for (int i = 0; i < 4; ++i) {
            gi[i][0] = sigmoidf_(acc[i][0] + bi4.x);
            gi[i][1] = sigmoidf_(acc[i][1] + bi4.y);
            gi[i][2] = sigmoidf_(acc[i][2] + bi4.z);
            gi[i][3] = sigmoidf_(acc[i][3] + bi4.w);
        }
    }
    __syncthreads();

    load_w128(sW, Wr, 128, tid);
    __syncthreads();
    ZERO44(acc);
    gemm_tile(sU, sW, acc, trow, tcol);

    float4 br4 = reinterpret_cast<const float4*>(br)[tcol];
    float4 lg4 = reinterpret_cast<const float4*>(g_loga)[tcol];
#pragma unroll
    for (int i = 0; i < 4; ++i) {
        int row = trow * 4 + i;
        size_t n = (size_t)(n0 + row);
        float4 uv = reinterpret_cast<const float4*>(sU + row * 128)[tcol];
        float gr0 = sigmoidf_(acc[i][0] + br4.x);
        float gr1 = sigmoidf_(acc[i][1] + br4.y);
        float gr2 = sigmoidf_(acc[i][2] + br4.z);
        float gr3 = sigmoidf_(acc[i][3] + br4.w);
        float4 av, bv;
        av.x = expf(8.f * gr0 * lg4.x);
        av.y = expf(8.f * gr1 * lg4.y);
        av.z = expf(8.f * gr2 * lg4.z);
        av.w = expf(8.f * gr3 * lg4.w);
        bv.x = sqrtf(fmaxf(0.f, 1.f - av.x * av.x)) * gi[i][0] * uv.x;
        bv.y = sqrtf(fmaxf(0.f, 1.f - av.y * av.y)) * gi[i][1] * uv.y;
        bv.z = sqrtf(fmaxf(0.f, 1.f - av.z * av.z)) * gi[i][2] * uv.z;
        bv.w = sqrtf(fmaxf(0.f, 1.f - av.w * av.w)) * gi[i][3] * uv.w;
        reinterpret_cast<float4*>(g_at + n * H)[tcol] = av;
        reinterpret_cast<float4*>(g_bt + n * H)[tcol] = bv;
    }
}

// ---------------- K2: chunk-local scan aggregates ----------------
__global__ void k_scan1() {
    int bc = blockIdx.x;      // b*NCH + ch; chunks tile tokens contiguously
    int h = threadIdx.x;
    size_t base = (size_t)bc * CL * H + h;
    float A = 1.f, hf = 0.f;
#pragma unroll 4
    for (int t = 0; t < CL; ++t) {
        size_t idx = base + (size_t)t * H;
        float a = g_at[idx], bb = g_bt[idx];
        A *= a;
        hf = fmaf(a, hf, bb);
    }
    float hb = 0.f;
#pragma unroll 4
    for (int t = CL - 1; t >= 0; --t) {
        size_t idx = base + (size_t)t * H;
        hb = fmaf(g_at[idx], hb, g_bt[idx]);
    }
    int o = bc * H + h;
    g_A[o] = A; g_Bf[o] = hf; g_Bb[o] = hb;
}

// ---------------- K3: cross-chunk carry scan (tiny) ----------------
__global__ void k_carry() {
    int b = blockIdx.x, h = threadIdx.x;
    float c = 0.f;
    for (int i = 0; i < NCH; ++i) {
        int o = (b * NCH + i) * H + h;
        g_cf[o] = c;
        c = fmaf(g_A[o], c, g_Bf[o]);
    }
    c = 0.f;
    for (int i = NCH - 1; i >= 0; --i) {
        int o = (b * NCH + i) * H + h;
        g_cb[o] = c;
        c = fmaf(g_A[o], c, g_Bb[o]);
    }
}

// ---------------- K4: final scans with carries ----------------
__global__ void k_scan2() {
    int bc = blockIdx.x;
    int h = threadIdx.x;
    size_t base = (size_t)bc * CL * H + h;
    float hf = g_cf[bc * H + h];
#pragma unroll 4
    for (int t = 0; t < CL; ++t) {
        size_t idx = base + (size_t)t * H;
        hf = fmaf(g_at[idx], hf, g_bt[idx]);
        g_hf[idx] = hf;
    }
    float hb = g_cb[bc * H + h];
#pragma unroll 4
    for (int t = CL - 1; t >= 0; --t) {
        size_t idx = base + (size_t)t * H;
        hb = fmaf(g_at[idx], hb, g_bt[idx]);
        g_hb[idx] = hb;
    }
}

// ---------------- K5: r = [hf|hb] @ Wout + bout; x1 = x + g1*r ----------------
__global__ __launch_bounds__(512) void k_rout(const float* __restrict__ x,
                                              const float* __restrict__ Wout,
                                              const float* __restrict__ bout) {
    extern __shared__ float sm[];
    float* sA = sm;            // 64x128
    float* sW = sm + 8192;     // 128x128
    int tid = threadIdx.x;
    int n0 = blockIdx.x * 64;
    int b = n0 >> 13;
    int tcol = tid & 31, trow = tid >> 5;
    float acc[4][4];
    ZERO44(acc);
    for (int half = 0; half < 2; ++half) {
        const float* src = half ? g_hb : g_hf;
        const float4* s4 = reinterpret_cast<const float4*>(src + (size_t)n0 * H);
        float4* a4 = reinterpret_cast<float4*>(sA);
#pragma unroll
        for (int i = 0; i < 4; ++i) a4[tid + i * 512] = s4[tid + i * 512];
        load_w128(sW, Wout + half * 128 * 128, 128, tid);
        __syncthreads();
        gemm_tile(sA, sW, acc, trow, tcol);
        __syncthreads();
    }
    float g1 = g_scal[b][2];
    float4 bo4 = reinterpret_cast<const float4*>(bout)[tcol];
#pragma unroll
    for (int i = 0; i < 4; ++i) {
        size_t n = (size_t)(n0 + trow * 4 + i);
        float4 xv = reinterpret_cast<const float4*>(x + n * D)[tcol];
        float4 o;
        o.x = fmaf(g1, acc[i][0] + bo4.x, xv.x);
        o.y = fmaf(g1, acc[i][1] + bo4.y, xv.y);
        o.z = fmaf(g1, acc[i][2] + bo4.z, xv.z);
        o.w = fmaf(g1, acc[i][3] + bo4.w, xv.w);
        reinterpret_cast<float4*>(g_x1 + n * D)[tcol] = o;
    }
}

// ---------------- K6: branch 2 (cond LN -> gelu MLP -> gated residual) ----------------
__global__ __launch_bounds__(512) void k_mlp(float* __restrict__ out,
                                             const float* __restrict__ W1,
                                             const float* __restrict__ b1m,
                                             const float* __restrict__ W2,
                                             const float* __restrict__ b2m) {
    extern __shared__ float sm[];
    float* sA = sm;            // 64x128 conditioned LN
    float* sT = sm + 8192;     // 64x128 gelu chunk
    float* sW = sm + 16384;    // 128x128 weights
    int tid = threadIdx.x;
    int lane = tid & 31, wid = tid >> 5;
    int n0 = blockIdx.x * 64;
    int b = n0 >> 13;
    float s2p = 1.f + g_scal[b][3];
    float b2s = g_scal[b][4];
    float g2 = g_scal[b][5];

#pragma unroll
    for (int it = 0; it < 4; ++it) {
        int row = wid * 4 + it;
        const float* xp = g_x1 + (size_t)(n0 + row) * D;
        float v0 = xp[lane], v1 = xp[lane + 32], v2 = xp[lane + 64], v3 = xp[lane + 96];
        float m = warp_sum(v0 + v1 + v2 + v3) * (1.f / 128.f);
        float d0 = v0 - m, d1 = v1 - m, d2 = v2 - m, d3 = v3 - m;
        float ss = warp_sum(d0*d0 + d1*d1 + d2*d2 + d3*d3);
        float rs = rsqrtf(ss * (1.f / 128.f) + 1e-6f);
        float* ap = sA + row * 128;
        ap[lane]      = fmaf(s2p, d0 * rs, b2s);
        ap[lane + 32] = fmaf(s2p, d1 * rs, b2s);
        ap[lane + 64] = fmaf(s2p, d2 * rs, b2s);
        ap[lane + 96] = fmaf(s2p, d3 * rs, b2s);
    }
    __syncthreads();

    int tcol = lane, trow = wid;
    float macc[4][4];
    ZERO44(macc);
    for (int nc = 0; nc < 4; ++nc) {
        load_w128(sW, W1 + nc * 128, 512, tid);
        __syncthreads();
        float tcc[4][4];
        ZERO44(tcc);
        gemm_tile(sA, sW, tcc, trow, tcol);
        float4 b14 = reinterpret_cast<const float4*>(b1m + nc * 128)[tcol];
#pragma unroll
        for (int i = 0; i < 4; ++i) {
            int row = trow * 4 + i;
            float4 tv;
            tv.x = geluf_(tcc[i][0] + b14.x);
            tv.y = geluf_(tcc[i][1] + b14.y);
            tv.z = geluf_(tcc[i][2] + b14.z);
            tv.w = geluf_(tcc[i][3] + b14.w);
            reinterpret_cast<float4*>(sT + row * 128)[tcol] = tv;
        }
        __syncthreads();
        load_w128(sW, W2 + nc * 128 * 128, 128, tid);
        __syncthreads();
        gemm_tile(sT, sW, macc, trow, tcol);
        __syncthreads();
    }
    float4 b24 = reinterpret_cast<const float4*>(b2m)[tcol];
#pragma unroll
    for (int i = 0; i < 4; ++i) {
        size_t n = (size_t)(n0 + trow * 4 + i);
        float4 xv = reinterpret_cast<const float4*>(g_x1 + n * D)[tcol];
        float4 o;
        o.x = fmaf(g2, macc[i][0] + b24.x, xv.x);
        o.y = fmaf(g2, macc[i][1] + b24.y, xv.y);
        o.z = fmaf(g2, macc[i][2] + b24.z, xv.z);
        o.w = fmaf(g2, macc[i][3] + b24.w, xv.w);
        reinterpret_cast<float4*>(out + n * D)[tcol] = o;
    }
}

// ---------------- launch ----------------
extern "C" void kernel_launch(void* const* d_in, const int* in_sizes, int n_in,
                              void* d_out, int out_size) {
    const float* x        = (const float*)d_in[0];
    const float* c        = (const float*)d_in[1];
    const float* cln1_sw  = (const float*)d_in[2];
    const float* cln1_sb  = (const float*)d_in[3];
    const float* cln1_bw  = (const float*)d_in[4];
    const float* cln1_bb  = (const float*)d_in[5];
    const float* gate1_w  = (const float*)d_in[6];
    const float* gate1_b  = (const float*)d_in[7];
    const float* rnn_in_w = (const float*)d_in[8];
    const float* rnn_in_b = (const float*)d_in[9];
    const float* pos_emb  = (const float*)d_in[10];
    const float* rnn_wi   = (const float*)d_in[11];
    const float* rnn_bi   = (const float*)d_in[12];
    const float* rnn_wr   = (const float*)d_in[13];
    const float* rnn_br   = (const float*)d_in[14];
    const float* rnn_a    = (const float*)d_in[15];
    const float* rnn_out_w= (const float*)d_in[16];
    const float* rnn_out_b= (const float*)d_in[17];
    const float* cln2_sw  = (const float*)d_in[18];
    const float* cln2_sb  = (const float*)d_in[19];
    const float* cln2_bw  = (const float*)d_in[20];
    const float* cln2_bb  = (const float*)d_in[21];
    const float* gate2_w  = (const float*)d_in[22];
    const float* gate2_b  = (const float*)d_in[23];
    const float* mlp_w1   = (const float*)d_in[24];
    const float* mlp_b1   = (const float*)d_in[25];
    const float* mlp_w2   = (const float*)d_in[26];
    const float* mlp_b2   = (const float*)d_in[27];
    float* out = (float*)d_out;

    cudaFuncSetAttribute(k_front, cudaFuncAttributeMaxDynamicSharedMemorySize, 131072);
    cudaFuncSetAttribute(k_rout,  cudaFuncAttributeMaxDynamicSharedMemorySize, 98304);
    cudaFuncSetAttribute(k_mlp,   cudaFuncAttributeMaxDynamicSharedMemorySize, 131072);

    k_scal<<<1, 256>>>(c, cln1_sw, cln1_sb, cln1_bw, cln1_bb, gate1_w, gate1_b,
                       cln2_sw, cln2_sb, cln2_bw, cln2_bb, gate2_w, gate2_b, rnn_a);
    k_front<<<NTOK / 64, 512, 131072>>>(x, rnn_in_w, rnn_in_b, pos_emb,
                                        rnn_wi, rnn_bi, rnn_wr, rnn_br);
    k_scan1<<<BS * NCH, H>>>();
    k_carry<<<BS, H>>>();
    k_scan2<<<BS * NCH, H>>>();
    k_rout<<<NTOK / 64, 512, 98304>>>(x, rnn_out_w, rnn_out_b);
    k_mlp<<<NTOK / 64, 512, 131072>>>(out, mlp_w1, mlp_b1, mlp_w2, mlp_b2);
}

// round 4
// speedup vs baseline: 1.0137x; 1.0137x over previous
#include <cuda_runtime.h>
#include <math.h>

#define BS   8
#define LSEQ 8192
#define D    128
#define H    128
#define DFF  512
#define NTOK (BS * LSEQ)   // 65536
#define CL   512
#define NCH  (LSEQ / CL)   // 16

// ---------------- device scratch (static; no runtime allocation) ----------------
__device__ __align__(16) float g_scal[BS][6];     // s1,b1,g1,s2,b2,g2 per batch
__device__ __align__(16) float g_loga[H];
__device__ __align__(16) float g_at[(size_t)NTOK * H];
__device__ __align__(16) float g_bt[(size_t)NTOK * H];
__device__ __align__(16) float g_hf[(size_t)NTOK * H];
__device__ __align__(16) float g_hb[(size_t)NTOK * H];
__device__ __align__(16) float g_x1[(size_t)NTOK * D];
__device__ __align__(16) float g_A [BS * NCH * H];
__device__ __align__(16) float g_Bf[BS * NCH * H];
__device__ __align__(16) float g_Bb[BS * NCH * H];
__device__ __align__(16) float g_cf[BS * NCH * H];
__device__ __align__(16) float g_cb[BS * NCH * H];

// ---------------- helpers ----------------
__device__ __forceinline__ float warp_sum(float v) {
    v += __shfl_xor_sync(0xffffffffu, v, 16);
    v += __shfl_xor_sync(0xffffffffu, v, 8);
    v += __shfl_xor_sync(0xffffffffu, v, 4);
    v += __shfl_xor_sync(0xffffffffu, v, 2);
    v += __shfl_xor_sync(0xffffffffu, v, 1);
    return v;
}

__device__ __forceinline__ float sigmoidf_(float v) {
    return 1.f / (1.f + expf(-v));
}

__device__ __forceinline__ float geluf_(float v) {
    // jax.nn.gelu default (approximate=True, tanh form)
    float v3 = v * v * v;
    return 0.5f * v * (1.f + tanhf(0.7978845608028654f * (v + 0.044715f * v3)));
}

// Load a 128x128 fp32 tile (row stride ldg floats) into smem [128][128]; 512 threads.
__device__ __forceinline__ void load_w128(float* sW, const float* __restrict__ g,
                                          int ldg, int tid) {
#pragma unroll
    for (int i = 0; i < 8; ++i) {
        int m = tid + i * 512;     // float4 index, 0..4095
        int k = m >> 5;            // row
        int j = m & 31;            // float4 within row
        reinterpret_cast<float4*>(sW)[m] =
            *reinterpret_cast<const float4*>(g + (size_t)k * ldg + j * 4);
    }
}

// C(64x128) += A(64x128 smem) * W(128x128 smem). 512 threads: trow=tid>>5 (16), tcol=tid&31 (32).
__device__ __forceinline__ void gemm_tile(const float* __restrict__ sA,
                                          const float* __restrict__ sW,
                                          float acc[4][4], int trow, int tcol) {
    const float* a0 = sA + (trow * 4 + 0) * 128;
    const float* a1 = sA + (trow * 4 + 1) * 128;
    const float* a2 = sA + (trow * 4 + 2) * 128;
    const float* a3 = sA + (trow * 4 + 3) * 128;
#pragma unroll 8
    for (int k = 0; k < 128; ++k) {
        float4 bv = reinterpret_cast<const float4*>(sW + k * 128)[tcol];
        float v0 = a0[k], v1 = a1[k], v2 = a2[k], v3 = a3[k];
        acc[0][0] = fmaf(v0, bv.x, acc[0][0]);
        acc[0][1] = fmaf(v0, bv.y, acc[0][1]);
        acc[0][2] = fmaf(v0, bv.z, acc[0][2]);
        acc[0][3] = fmaf(v0, bv.w, acc[0][3]);
        acc[1][0] = fmaf(v1, bv.x, acc[1][0]);
        acc[1][1] = fmaf(v1, bv.y, acc[1][1]);
        acc[1][2] = fmaf(v1, bv.z, acc[1][2]);
        acc[1][3] = fmaf(v1, bv.w, acc[1][3]);
        acc[2][0] = fmaf(v2, bv.x, acc[2][0]);
        acc[2][1] = fmaf(v2, bv.y, acc[2][1]);
        acc[2][2] = fmaf(v2, bv.z, acc[2][2]);
        acc[2][3] = fmaf(v2, bv.w, acc[2][3]);
        acc[3][0] = fmaf(v3, bv.x, acc[3][0]);
        acc[3][1] = fmaf(v3, bv.y, acc[3][1]);
        acc[3][2] = fmaf(v3, bv.z, acc[3][2]);
        acc[3][3] = fmaf(v3, bv.w, acc[3][3]);
    }
}

#define ZERO44(a) do { _Pragma("unroll") for (int _i=0;_i<4;++_i) { _Pragma("unroll") for (int _j=0;_j<4;++_j) (a)[_i][_j]=0.f; } } while(0)

// ---------------- K0: per-batch conditioning scalars + log(a) ----------------
__global__ void k_scal(const float* __restrict__ c,
                       const float* sw1, const float* sb1,
                       const float* bw1, const float* bb1,
                       const float* gw1, const float* gb1,
                       const float* sw2, const float* sb2,
                       const float* bw2, const float* bb2,
                       const float* gw2, const float* gb2,
                       const float* __restrict__ a) {
    int tid = threadIdx.x;
    if (tid < 48) {
        const float* ws[6] = {sw1, bw1, gw1, sw2, bw2, gw2};
        const float* bs[6] = {sb1, bb1, gb1, sb2, bb2, gb2};
        int b = tid / 6, j = tid % 6;
        float s = bs[j][0];
        const float* cp = c + b * 128;
        for (int k = 0; k < 128; ++k) s = fmaf(cp[k], ws[j][k], s);
        g_scal[b][j] = s;
    }
    int i = tid - 64;
    if (i >= 0 && i < H) g_loga[i] = logf(a[i]);
}

// ---------------- K1: x -> (at, bt)  [2 LNs + 3 GEMMs fused] ----------------
__global__ __launch_bounds__(512) void k_front(
    const float* __restrict__ x, const float* __restrict__ Win,
    const float* __restrict__ inb, const float* __restrict__ pos,
    const float* __restrict__ Wi, const float* __restrict__ bi,
    const float* __restrict__ Wr, const float* __restrict__ br) {
    extern __shared__ float sm[];
    float* sA = sm;             // 64x128 ln2
    float* sU = sm + 8192;      // 64x128 u
    float* sW = sm + 16384;     // 128x128 weights
    int tid = threadIdx.x;
    int lane = tid & 31, wid = tid >> 5;
    int n0 = blockIdx.x * 64;
    int b  = n0 >> 13;
    int l0 = n0 & (LSEQ - 1);
    float s1p = 1.f + g_scal[b][0];
    float b1s = g_scal[b][1];

    // double LayerNorm with conditioning, one token per warp per iter
#pragma unroll
    for (int it = 0; it < 4; ++it) {
        int row = wid * 4 + it;
        const float* xp = x + (size_t)(n0 + row) * D;
        float v0 = xp[lane], v1 = xp[lane + 32], v2 = xp[lane + 64], v3 = xp[lane + 96];
        float m = warp_sum(v0 + v1 + v2 + v3) * (1.f / 128.f);
        float d0 = v0 - m, d1 = v1 - m, d2 = v2 - m, d3 = v3 - m;
        float ss = warp_sum(d0*d0 + d1*d1 + d2*d2 + d3*d3);
        float rs = rsqrtf(ss * (1.f / 128.f) + 1e-6f);
        float h0 = fmaf(s1p, d0 * rs, b1s), h1 = fmaf(s1p, d1 * rs, b1s);
        float h2 = fmaf(s1p, d2 * rs, b1s), h3 = fmaf(s1p, d3 * rs, b1s);
        float m2 = warp_sum(h0 + h1 + h2 + h3) * (1.f / 128.f);
        float e0 = h0 - m2, e1 = h1 - m2, e2 = h2 - m2, e3 = h3 - m2;
        float ss2 = warp_sum(e0*e0 + e1*e1 + e2*e2 + e3*e3);
        float rs2 = rsqrtf(ss2 * (1.f / 128.f) + 1e-6f);
        float* ap = sA + row * 128;
        ap[lane]      = e0 * rs2;
        ap[lane + 32] = e1 * rs2;
        ap[lane + 64] = e2 * rs2;
        ap[lane + 96] = e3 * rs2;
    }
    load_w128(sW, Win, 128, tid);
    __syncthreads();

    int tcol = lane, trow = wid;
    float acc[4][4];
    ZERO44(acc);
    gemm_tile(sA, sW, acc, trow, tcol);

    // u = ln2 @ Win + in_b + pos
    float4 ib4 = reinterpret_cast<const float4*>(inb)[tcol];
#pragma unroll
    for (int i = 0; i < 4; ++i) {
        int row = trow * 4 + i;
        float4 pv = reinterpret_cast<const float4*>(pos + (size_t)(l0 + row) * H)[tcol];
        float4 uv;
        uv.x = acc[i][0] + ib4.x + pv.x;
        uv.y = acc[i][1] + ib4.y + pv.y;
        uv.z = acc[i][2] + ib4.z + pv.z;
        uv.w = acc[i][3] + ib4.w + pv.w;
        reinterpret_cast<float4*>(sU + row * 128)[tcol] = uv;
    }
    __syncthreads();

    load_w128(sW, Wi, 128, tid);
    __syncthreads();
    ZERO44(acc);
    gemm_tile(sU, sW, acc, trow, tcol);
    float gi[4][4];
    {
        float4 bi4 = reinterpret_cast<const float4*>(bi)[tcol];
#pragma unroll
        for (int i = 0; i < 4; ++i) {
            gi[i][0] = sigmoidf_(acc[i][0] + bi4.x);
            gi[i][1] = sigmoidf_(acc[i][1] + bi4.y);
            gi[i][2] = sigmoidf_(acc[i][2] + bi4.z);
            gi[i][3] = sigmoidf_(acc[i][3] + bi4.w);
        }
    }
    __syncthreads();

    load_w128(sW, Wr, 128, tid);
    __syncthreads();
    ZERO44(acc);
    gemm_tile(sU, sW, acc, trow, tcol);

    float4 br4 = reinterpret_cast<const float4*>(br)[tcol];
    float4 lg4 = reinterpret_cast<const float4*>(g_loga)[tcol];
#pragma unroll
    for (int i = 0; i < 4; ++i) {
        int row = trow * 4 + i;
        size_t n = (size_t)(n0 + row);
        float4 uv = reinterpret_cast<const float4*>(sU + row * 128)[tcol];
        float gr0 = sigmoidf_(acc[i][0] + br4.x);
        float gr1 = sigmoidf_(acc[i][1] + br4.y);
        float gr2 = sigmoidf_(acc[i][2] + br4.z);
        float gr3 = sigmoidf_(acc[i][3] + br4.w);
        float4 av, bv;
        av.x = expf(8.f * gr0 * lg4.x);
        av.y = expf(8.f * gr1 * lg4.y);
        av.z = expf(8.f * gr2 * lg4.z);
        av.w = expf(8.f * gr3 * lg4.w);
        bv.x = sqrtf(fmaxf(0.f, 1.f - av.x * av.x)) * gi[i][0] * uv.x;
        bv.y = sqrtf(fmaxf(0.f, 1.f - av.y * av.y)) * gi[i][1] * uv.y;
        bv.z = sqrtf(fmaxf(0.f, 1.f - av.z * av.z)) * gi[i][2] * uv.z;
        bv.w = sqrtf(fmaxf(0.f, 1.f - av.w * av.w)) * gi[i][3] * uv.w;
        reinterpret_cast<float4*>(g_at + n * H)[tcol] = av;
        reinterpret_cast<float4*>(g_bt + n * H)[tcol] = bv;
    }
}

// ---------------- K2: chunk-local scan aggregates ----------------
__global__ void k_scan1() {
    int bc = blockIdx.x;      // b*NCH + ch; chunks tile tokens contiguously
    int h = threadIdx.x;
    size_t base = (size_t)bc * CL * H + h;
    float A = 1.f, hf = 0.f;
#pragma unroll 4
    for (int t = 0; t < CL; ++t) {
        size_t idx = base + (size_t)t * H;
        float a = g_at[idx], bb = g_bt[idx];
        A *= a;
        hf = fmaf(a, hf, bb);
    }
    float hb = 0.f;
#pragma unroll 4
    for (int t = CL - 1; t >= 0; --t) {
        size_t idx = base + (size_t)t * H;
        hb = fmaf(g_at[idx], hb, g_bt[idx]);
    }
    int o = bc * H + h;
    g_A[o] = A; g_Bf[o] = hf; g_Bb[o] = hb;
}

// ---------------- K3: cross-chunk carry scan (tiny) ----------------
__global__ void k_carry() {
    int b = blockIdx.x, h = threadIdx.x;
    float c = 0.f;
    for (int i = 0; i < NCH; ++i) {
        int o = (b * NCH + i) * H + h;
        g_cf[o] = c;
        c = fmaf(g_A[o], c, g_Bf[o]);
    }
    c = 0.f;
    for (int i = NCH - 1; i >= 0; --i) {
        int o = (b * NCH + i) * H + h;
        g_cb[o] = c;
        c = fmaf(g_A[o], c, g_Bb[o]);
    }
}

// ---------------- K4: final scans with carries ----------------
__global__ void k_scan2() {
    int bc = blockIdx.x;
    int h = threadIdx.x;
    size_t base = (size_t)bc * CL * H + h;
    float hf = g_cf[bc * H + h];
#pragma unroll 4
    for (int t = 0; t < CL; ++t) {
        size_t idx = base + (size_t)t * H;
        hf = fmaf(g_at[idx], hf, g_bt[idx]);
        g_hf[idx] = hf;
    }
    float hb = g_cb[bc * H + h];
#pragma unroll 4
    for (int t = CL - 1; t >= 0; --t) {
        size_t idx = base + (size_t)t * H;
        hb = fmaf(g_at[idx], hb, g_bt[idx]);
        g_hb[idx] = hb;
    }
}

// ---------------- K5: r = [hf|hb] @ Wout + bout; x1 = x + g1*r ----------------
__global__ __launch_bounds__(512) void k_rout(const float* __restrict__ x,
                                              const float* __restrict__ Wout,
                                              const float* __restrict__ bout) {
    extern __shared__ float sm[];
    float* sA = sm;            // 64x128
    float* sW = sm + 8192;     // 128x128
    int tid = threadIdx.x;
    int n0 = blockIdx.x * 64;
    int b = n0 >> 13;
    int tcol = tid & 31, trow = tid >> 5;
    float acc[4][4];
    ZERO44(acc);
    for (int half = 0; half < 2; ++half) {
        const float* src = half ? g_hb : g_hf;
        const float4* s4 = reinterpret_cast<const float4*>(src + (size_t)n0 * H);
        float4* a4 = reinterpret_cast<float4*>(sA);
#pragma unroll
        for (int i = 0; i < 4; ++i) a4[tid + i * 512] = s4[tid + i * 512];
        load_w128(sW, Wout + half * 128 * 128, 128, tid);
        __syncthreads();
        gemm_tile(sA, sW, acc, trow, tcol);
        __syncthreads();
    }
    float g1 = g_scal[b][2];
    float4 bo4 = reinterpret_cast<const float4*>(bout)[tcol];
#pragma unroll
    for (int i = 0; i < 4; ++i) {
        size_t n = (size_t)(n0 + trow * 4 + i);
        float4 xv = reinterpret_cast<const float4*>(x + n * D)[tcol];
        float4 o;
        o.x = fmaf(g1, acc[i][0] + bo4.x, xv.x);
        o.y = fmaf(g1, acc[i][1] + bo4.y, xv.y);
        o.z = fmaf(g1, acc[i][2] + bo4.z, xv.z);
        o.w = fmaf(g1, acc[i][3] + bo4.w, xv.w);
        reinterpret_cast<float4*>(g_x1 + n * D)[tcol] = o;
    }
}

// ---------------- K6: branch 2 (cond LN -> gelu MLP -> gated residual) ----------------
__global__ __launch_bounds__(512) void k_mlp(float* __restrict__ out,
                                             const float* __restrict__ W1,
                                             const float* __restrict__ b1m,
                                             const float* __restrict__ W2,
                                             const float* __restrict__ b2m) {
    extern __shared__ float sm[];
    float* sA = sm;            // 64x128 conditioned LN
    float* sT = sm + 8192;     // 64x128 gelu chunk
    float* sW = sm + 16384;    // 128x128 weights
    int tid = threadIdx.x;
    int lane = tid & 31, wid = tid >> 5;
    int n0 = blockIdx.x * 64;
    int b = n0 >> 13;
    float s2p = 1.f + g_scal[b][3];
    float b2s = g_scal[b][4];
    float g2 = g_scal[b][5];

#pragma unroll
    for (int it = 0; it < 4; ++it) {
        int row = wid * 4 + it;
        const float* xp = g_x1 + (size_t)(n0 + row) * D;
        float v0 = xp[lane], v1 = xp[lane + 32], v2 = xp[lane + 64], v3 = xp[lane + 96];
        float m = warp_sum(v0 + v1 + v2 + v3) * (1.f / 128.f);
        float d0 = v0 - m, d1 = v1 - m, d2 = v2 - m, d3 = v3 - m;
        float ss = warp_sum(d0*d0 + d1*d1 + d2*d2 + d3*d3);
        float rs = rsqrtf(ss * (1.f / 128.f) + 1e-6f);
        float* ap = sA + row * 128;
        ap[lane]      = fmaf(s2p, d0 * rs, b2s);
        ap[lane + 32] = fmaf(s2p, d1 * rs, b2s);
        ap[lane + 64] = fmaf(s2p, d2 * rs, b2s);
        ap[lane + 96] = fmaf(s2p, d3 * rs, b2s);
    }
    __syncthreads();

    int tcol = lane, trow = wid;
    float macc[4][4];
    ZERO44(macc);
    for (int nc = 0; nc < 4; ++nc) {
        load_w128(sW, W1 + nc * 128, 512, tid);
        __syncthreads();
        float tcc[4][4];
        ZERO44(tcc);
        gemm_tile(sA, sW, tcc, trow, tcol);
        float4 b14 = reinterpret_cast<const float4*>(b1m + nc * 128)[tcol];
#pragma unroll
        for (int i = 0; i < 4; ++i) {
            int row = trow * 4 + i;
            float4 tv;
            tv.x = geluf_(tcc[i][0] + b14.x);
            tv.y = geluf_(tcc[i][1] + b14.y);
            tv.z = geluf_(tcc[i][2] + b14.z);
            tv.w = geluf_(tcc[i][3] + b14.w);
            reinterpret_cast<float4*>(sT + row * 128)[tcol] = tv;
        }
        __syncthreads();
        load_w128(sW, W2 + nc * 128 * 128, 128, tid);
        __syncthreads();
        gemm_tile(sT, sW, macc, trow, tcol);
        __syncthreads();
    }
    float4 b24 = reinterpret_cast<const float4*>(b2m)[tcol];
#pragma unroll
    for (int i = 0; i < 4; ++i) {
        size_t n = (size_t)(n0 + trow * 4 + i);
        float4 xv = reinterpret_cast<const float4*>(g_x1 + n * D)[tcol];
        float4 o;
        o.x = fmaf(g2, macc[i][0] + b24.x, xv.x);
        o.y = fmaf(g2, macc[i][1] + b24.y, xv.y);
        o.z = fmaf(g2, macc[i][2] + b24.z, xv.z);
        o.w = fmaf(g2, macc[i][3] + b24.w, xv.w);
        reinterpret_cast<float4*>(out + n * D)[tcol] = o;
    }
}

// ---------------- launch ----------------
extern "C" void kernel_launch(void* const* d_in, const int* in_sizes, int n_in,
                              void* d_out, int out_size) {
    const float* x        = (const float*)d_in[0];
    const float* c        = (const float*)d_in[1];
    const float* cln1_sw  = (const float*)d_in[2];
    const float* cln1_sb  = (const float*)d_in[3];
    const float* cln1_bw  = (const float*)d_in[4];
    const float* cln1_bb  = (const float*)d_in[5];
    const float* gate1_w  = (const float*)d_in[6];
    const float* gate1_b  = (const float*)d_in[7];
    const float* rnn_in_w = (const float*)d_in[8];
    const float* rnn_in_b = (const float*)d_in[9];
    const float* pos_emb  = (const float*)d_in[10];
    const float* rnn_wi   = (const float*)d_in[11];
    const float* rnn_bi   = (const float*)d_in[12];
    const float* rnn_wr   = (const float*)d_in[13];
    const float* rnn_br   = (const float*)d_in[14];
    const float* rnn_a    = (const float*)d_in[15];
    const float* rnn_out_w= (const float*)d_in[16];
    const float* rnn_out_b= (const float*)d_in[17];
    const float* cln2_sw  = (const float*)d_in[18];
    const float* cln2_sb  = (const float*)d_in[19];
    const float* cln2_bw  = (const float*)d_in[20];
    const float* cln2_bb  = (const float*)d_in[21];
    const float* gate2_w  = (const float*)d_in[22];
    const float* gate2_b  = (const float*)d_in[23];
    const float* mlp_w1   = (const float*)d_in[24];
    const float* mlp_b1   = (const float*)d_in[25];
    const float* mlp_w2   = (const float*)d_in[26];
    const float* mlp_b2   = (const float*)d_in[27];
    float* out = (float*)d_out;

    cudaFuncSetAttribute(k_front, cudaFuncAttributeMaxDynamicSharedMemorySize, 131072);
    cudaFuncSetAttribute(k_rout,  cudaFuncAttributeMaxDynamicSharedMemorySize, 98304);
    cudaFuncSetAttribute(k_mlp,   cudaFuncAttributeMaxDynamicSharedMemorySize, 131072);

    k_scal<<<1, 256>>>(c, cln1_sw, cln1_sb, cln1_bw, cln1_bb, gate1_w, gate1_b,
                       cln2_sw, cln2_sb, cln2_bw, cln2_bb, gate2_w, gate2_b, rnn_a);
    k_front<<<NTOK / 64, 512, 131072>>>(x, rnn_in_w, rnn_in_b, pos_emb,
                                        rnn_wi, rnn_bi, rnn_wr, rnn_br);
    k_scan1<<<BS * NCH, H>>>();
    k_carry<<<BS, H>>>();
    k_scan2<<<BS * NCH, H>>>();
    k_rout<<<NTOK / 64, 512, 98304>>>(x, rnn_out_w, rnn_out_b);
    k_mlp<<<NTOK / 64, 512, 131072>>>(out, mlp_w1, mlp_b1, mlp_w2, mlp_b2);
}

// round 7
// speedup vs baseline: 1.7370x; 1.7135x over previous
#include <cuda_runtime.h>
#include <math.h>
#include <stdint.h>

#define BS   8
#define LSEQ 8192
#define D    128
#define H    128
#define NTOK (BS * LSEQ)
#define CL   256
#define NCH  (LSEQ / CL)   // 32

#define STRIDE    132                       // floats per smem tile row
#define TILE_B    (128 * STRIDE * 4)        // 67584 bytes
#define OFF_BIAS  0
#define OFF_A     4096
#define OFF_B     (OFF_A + TILE_B)
#define OFF_C     (OFF_B + TILE_B)
#define SMEM_SZ   (OFF_C + TILE_B)          // 206848

// ---------------- device scratch ----------------
__device__ __align__(16) float g_scal[BS][6];
__device__ __align__(16) float g_loga[H];          // log2(a)
__device__ __align__(16) float g_WT[13][16384];    // transposed tf32 weights [n][k]
__device__ __align__(16) float g_at[(size_t)NTOK * H];
__device__ __align__(16) float g_bt[(size_t)NTOK * H];
__device__ __align__(16) float g_hf[(size_t)NTOK * H];
__device__ __align__(16) float g_hb[(size_t)NTOK * H];
__device__ __align__(16) float g_x1[(size_t)NTOK * D];
__device__ __align__(16) float g_A [BS * NCH * H];
__device__ __align__(16) float g_Bf[BS * NCH * H];
__device__ __align__(16) float g_Bb[BS * NCH * H];
__device__ __align__(16) float g_cf[BS * NCH * H];
__device__ __align__(16) float g_cb[BS * NCH * H];

// ---------------- helpers ----------------
__device__ __forceinline__ float to_tf32(float x) {
    uint32_t u;
    asm("cvt.rna.tf32.f32 %0, %1;" : "=r"(u) : "f"(x));
    return __uint_as_float(u);
}
__device__ __forceinline__ float fast_ex2(float x) { float y; asm("ex2.approx.f32 %0, %1;" : "=f"(y) : "f"(x)); return y; }
__device__ __forceinline__ float fast_rcp(float x) { float y; asm("rcp.approx.f32 %0, %1;" : "=f"(y) : "f"(x)); return y; }
__device__ __forceinline__ float sigf(float v) { return fast_rcp(1.f + fast_ex2(-1.4426950408889634f * v)); }
__device__ __forceinline__ float tanh_(float x) { return 1.f - 2.f * fast_rcp(1.f + fast_ex2(2.8853900817779268f * x)); }
__device__ __forceinline__ float geluf_(float v) {
    float v3 = v * v * v;
    return 0.5f * v * (1.f + tanh_(0.7978845608028654f * (v + 0.044715f * v3)));
}
__device__ __forceinline__ float warp_sum(float v) {
    v += __shfl_xor_sync(0xffffffffu, v, 16);
    v += __shfl_xor_sync(0xffffffffu, v, 8);
    v += __shfl_xor_sync(0xffffffffu, v, 4);
    v += __shfl_xor_sync(0xffffffffu, v, 2);
    v += __shfl_xor_sync(0xffffffffu, v, 1);
    return v;
}

#define MMA168(c, a, b0, b1)                                                        \
    asm volatile("mma.sync.aligned.m16n8k8.row.col.f32.tf32.tf32.f32 "              \
                 "{%0,%1,%2,%3}, {%4,%5,%6,%7}, {%8,%9}, {%0,%1,%2,%3};"            \
                 : "+f"((c)[0]), "+f"((c)[1]), "+f"((c)[2]), "+f"((c)[3])           \
                 : "r"((a)[0]), "r"((a)[1]), "r"((a)[2]), "r"((a)[3]),              \
                   "r"(b0), "r"(b1))

#define ZACC(a) do {                                                                \
    _Pragma("unroll") for (int _m = 0; _m < 4; ++_m)                                \
    _Pragma("unroll") for (int _n = 0; _n < 4; ++_n)                                \
    _Pragma("unroll") for (int _q = 0; _q < 4; ++_q) (a)[_m][_n][_q] = 0.f;         \
} while (0)

// warp GEMM: 64x32 patch of C(128x128) += A(128x128) * B^T stored [n][k]
__device__ __forceinline__ void wgemm(const float* __restrict__ sA,
                                      const float* __restrict__ sB,
                                      float (&acc)[4][4][4],
                                      int wm, int wn, int tr, int tc) {
#pragma unroll 4
    for (int ks = 0; ks < 16; ++ks) {
        int k0 = ks * 8;
        uint32_t a[4][4];
#pragma unroll
        for (int mt = 0; mt < 4; ++mt) {
            const float* ap = sA + (wm * 64 + mt * 16 + tr) * STRIDE + k0 + tc;
            a[mt][0] = __float_as_uint(ap[0]);
            a[mt][1] = __float_as_uint(ap[8 * STRIDE]);
            a[mt][2] = __float_as_uint(ap[4]);
            a[mt][3] = __float_as_uint(ap[8 * STRIDE + 4]);
        }
#pragma unroll
        for (int nt = 0; nt < 4; ++nt) {
            const float* bp = sB + (wn * 32 + nt * 8 + tr) * STRIDE + k0 + tc;
            uint32_t b0 = __float_as_uint(bp[0]);
            uint32_t b1 = __float_as_uint(bp[4]);
#pragma unroll
            for (int mt = 0; mt < 4; ++mt) MMA168(acc[mt][nt], a[mt], b0, b1);
        }
    }
}

// copy a prepared 128x128 tf32 tile (contiguous) into smem with STRIDE rows
__device__ __forceinline__ void cp_tileT(float* dst, const float* __restrict__ src, int tid) {
#pragma unroll
    for (int it = 0; it < 16; ++it) {
        int idx = tid + it * 256;              // float4 index
        int row = idx >> 5, j = idx & 31;
        *(float4*)(dst + row * STRIDE + j * 4) = ((const float4*)src)[idx];
    }
}
// stage a 128x128 fp32 activation tile (row-major, stride 128) -> tf32 smem tile
__device__ __forceinline__ void stage_act(float* dst, const float* __restrict__ g, int tid) {
#pragma unroll
    for (int it = 0; it < 16; ++it) {
        int idx = tid + it * 256;
        int row = idx >> 5, j4 = (idx & 31) << 2;
        float4 v = *(const float4*)(g + (size_t)row * 128 + j4);
        float4 o;
        o.x = to_tf32(v.x); o.y = to_tf32(v.y); o.z = to_tf32(v.z); o.w = to_tf32(v.w);
        *(float4*)(dst + row * STRIDE + j4) = o;
    }
}

// ---------------- K0: conditioning scalars + log2(a) ----------------
__global__ void k_scal(const float* __restrict__ c,
                       const float* sw1, const float* sb1, const float* bw1, const float* bb1,
                       const float* gw1, const float* gb1, const float* sw2, const float* sb2,
                       const float* bw2, const float* bb2, const float* gw2, const float* gb2,
                       const float* __restrict__ a) {
    int tid = threadIdx.x;
    if (tid < 48) {
        const float* ws[6] = {sw1, bw1, gw1, sw2, bw2, gw2};
        const float* bs[6] = {sb1, bb1, gb1, sb2, bb2, gb2};
        int b = tid / 6, j = tid % 6;
        float s = bs[j][0];
        const float* cp = c + b * 128;
        for (int k = 0; k < 128; ++k) s = fmaf(cp[k], ws[j][k], s);
        g_scal[b][j] = s;
    }
    int i = tid - 64;
    if (i >= 0 && i < H) g_loga[i] = log2f(a[i]);
}

// ---------------- K-prep: transposed tf32 weight tiles ----------------
// 0=Win 1=Wi 2=Wr 3=Wout(k<128) 4=Wout(k>=128) 5..8=W1 chunks 9..12=W2 chunks
__global__ void k_prep(const float* __restrict__ Win, const float* __restrict__ Wi,
                       const float* __restrict__ Wr, const float* __restrict__ Wout,
                       const float* __restrict__ W1, const float* __restrict__ W2) {
    int t = blockIdx.x, tid = threadIdx.x;
    for (int i = 0; i < 64; ++i) {
        int e = i * 256 + tid;
        int n = e >> 7, k = e & 127;
        float v;
        if (t == 0)      v = Win[k * 128 + n];
        else if (t == 1) v = Wi[k * 128 + n];
        else if (t == 2) v = Wr[k * 128 + n];
        else if (t == 3) v = Wout[k * 128 + n];
        else if (t == 4) v = Wout[(128 + k) * 128 + n];
        else if (t < 9)  v = W1[k * 512 + (t - 5) * 128 + n];
        else             v = W2[((t - 9) * 128 + k) * 128 + n];
        g_WT[t][n * 128 + k] = to_tf32(v);
    }
}

// ---------------- K1: x -> (at, bt) ----------------
__global__ __launch_bounds__(256, 1) void k_front(
    const float* __restrict__ x, const float* __restrict__ pos,
    const float* __restrict__ inb, const float* __restrict__ bi,
    const float* __restrict__ br) {
    extern __shared__ char sm[];
    float* sBias = (float*)(sm + OFF_BIAS);
    float* sA = (float*)(sm + OFF_A);
    float* sB = (float*)(sm + OFF_B);
    float* sC = (float*)(sm + OFF_C);
    int tid = threadIdx.x, wid = tid >> 5, lane = tid & 31;
    int wm = wid & 1, wn = wid >> 1, tr = lane >> 2, tc = lane & 3;
    int n0 = blockIdx.x * 128;
    int b = n0 >> 13, l0 = n0 & (LSEQ - 1);
    if (tid < 128) {
        sBias[tid] = inb[tid]; sBias[128 + tid] = bi[tid];
        sBias[256 + tid] = br[tid]; sBias[384 + tid] = g_loga[tid];
    }
    float s1p = 1.f + g_scal[b][0], b1s = g_scal[b][1];

    // conditioned double-LN -> tf32 A tile
    for (int it = 0; it < 16; ++it) {
        int row = wid * 16 + it;
        const float* xp = x + (size_t)(n0 + row) * D;
        float v0 = xp[lane], v1 = xp[lane + 32], v2 = xp[lane + 64], v3 = xp[lane + 96];
        float m = warp_sum(v0 + v1 + v2 + v3) * (1.f / 128.f);
        float d0 = v0 - m, d1 = v1 - m, d2 = v2 - m, d3 = v3 - m;
        float rs = rsqrtf(warp_sum(d0*d0 + d1*d1 + d2*d2 + d3*d3) * (1.f / 128.f) + 1e-6f);
        float h0 = fmaf(s1p, d0 * rs, b1s), h1 = fmaf(s1p, d1 * rs, b1s);
        float h2 = fmaf(s1p, d2 * rs, b1s), h3 = fmaf(s1p, d3 * rs, b1s);
        float m2 = warp_sum(h0 + h1 + h2 + h3) * (1.f / 128.f);
        float e0 = h0 - m2, e1 = h1 - m2, e2 = h2 - m2, e3 = h3 - m2;
        float rs2 = rsqrtf(warp_sum(e0*e0 + e1*e1 + e2*e2 + e3*e3) * (1.f / 128.f) + 1e-6f);
        float* ap = sA + row * STRIDE;
        ap[lane]      = to_tf32(e0 * rs2);
        ap[lane + 32] = to_tf32(e1 * rs2);
        ap[lane + 64] = to_tf32(e2 * rs2);
        ap[lane + 96] = to_tf32(e3 * rs2);
    }
    cp_tileT(sB, g_WT[0], tid);
    __syncthreads();

    float uacc[4][4][4];
    ZACC(uacc);
    wgemm(sA, sB, uacc, wm, wn, tr, tc);
    __syncthreads();                       // all warps done reading sA

    // u = gemm + bias + pos -> tf32 back into sA
#pragma unroll
    for (int mt = 0; mt < 4; ++mt)
#pragma unroll
        for (int nt = 0; nt < 4; ++nt) {
            int r = wm * 64 + mt * 16 + tr, c = wn * 32 + nt * 8 + tc * 2;
            float2 p0 = *(const float2*)(pos + (size_t)(l0 + r) * H + c);
            float2 p1 = *(const float2*)(pos + (size_t)(l0 + r + 8) * H + c);
            sA[r * STRIDE + c]           = to_tf32(uacc[mt][nt][0] + sBias[c]     + p0.x);
            sA[r * STRIDE + c + 1]       = to_tf32(uacc[mt][nt][1] + sBias[c + 1] + p0.y);
            sA[(r + 8) * STRIDE + c]     = to_tf32(uacc[mt][nt][2] + sBias[c]     + p1.x);
            sA[(r + 8) * STRIDE + c + 1] = to_tf32(uacc[mt][nt][3] + sBias[c + 1] + p1.y);
        }
    cp_tileT(sB, g_WT[1], tid);
    cp_tileT(sC, g_WT[2], tid);
    __syncthreads();

    float gacc[4][4][4];
    ZACC(gacc);
    wgemm(sA, sB, gacc, wm, wn, tr, tc);   // input gate pre-activation
#pragma unroll
    for (int mt = 0; mt < 4; ++mt)
#pragma unroll
        for (int nt = 0; nt < 4; ++nt) {
            int c = wn * 32 + nt * 8 + tc * 2;
            gacc[mt][nt][0] = sigf(gacc[mt][nt][0] + sBias[128 + c]);
            gacc[mt][nt][1] = sigf(gacc[mt][nt][1] + sBias[128 + c + 1]);
            gacc[mt][nt][2] = sigf(gacc[mt][nt][2] + sBias[128 + c]);
            gacc[mt][nt][3] = sigf(gacc[mt][nt][3] + sBias[128 + c + 1]);
        }
    float racc[4][4][4];
    ZACC(racc);
    wgemm(sA, sC, racc, wm, wn, tr, tc);   // recurrence gate pre-activation

#pragma unroll
    for (int mt = 0; mt < 4; ++mt)
#pragma unroll
        for (int nt = 0; nt < 4; ++nt) {
            int r = wm * 64 + mt * 16 + tr, c = wn * 32 + nt * 8 + tc * 2;
            float2 u0 = *(const float2*)(sA + r * STRIDE + c);
            float2 u1 = *(const float2*)(sA + (r + 8) * STRIDE + c);
            float la0 = sBias[384 + c], la1 = sBias[384 + c + 1];
            float gr0 = sigf(racc[mt][nt][0] + sBias[256 + c]);
            float gr1 = sigf(racc[mt][nt][1] + sBias[256 + c + 1]);
            float gr2 = sigf(racc[mt][nt][2] + sBias[256 + c]);
            float gr3 = sigf(racc[mt][nt][3] + sBias[256 + c + 1]);
            float a0 = fast_ex2(8.f * gr0 * la0);
            float a1 = fast_ex2(8.f * gr1 * la1);
            float a2 = fast_ex2(8.f * gr2 * la0);
            float a3 = fast_ex2(8.f * gr3 * la1);
            float b0v = sqrtf(fmaxf(0.f, 1.f - a0 * a0)) * gacc[mt][nt][0] * u0.x;
            float b1v = sqrtf(fmaxf(0.f, 1.f - a1 * a1)) * gacc[mt][nt][1] * u0.y;
            float b2v = sqrtf(fmaxf(0.f, 1.f - a2 * a2)) * gacc[mt][nt][2] * u1.x;
            float b3v = sqrtf(fmaxf(0.f, 1.f - a3 * a3)) * gacc[mt][nt][3] * u1.y;
            size_t o0 = (size_t)(n0 + r) * H + c, o1 = (size_t)(n0 + r + 8) * H + c;
            *(float2*)(g_at + o0) = make_float2(a0, a1);
            *(float2*)(g_at + o1) = make_float2(a2, a3);
            *(float2*)(g_bt + o0) = make_float2(b0v, b1v);
            *(float2*)(g_bt + o1) = make_float2(b2v, b3v);
        }
}

// ---------------- scans (fp32) ----------------
__global__ void k_scan1() {
    int bc = blockIdx.x, h = threadIdx.x;
    size_t base = (size_t)bc * CL * H + h;
    float A = 1.f, hf = 0.f;
#pragma unroll 4
    for (int t = 0; t < CL; ++t) {
        size_t idx = base + (size_t)t * H;
        float a = g_at[idx], bb = g_bt[idx];
        A *= a;
        hf = fmaf(a, hf, bb);
    }
    float hb = 0.f;
#pragma unroll 4
    for (int t = CL - 1; t >= 0; --t) {
        size_t idx = base + (size_t)t * H;
        hb = fmaf(g_at[idx], hb, g_bt[idx]);
    }
    int o = bc * H + h;
    g_A[o] = A; g_Bf[o] = hf; g_Bb[o] = hb;
}
__global__ void k_carry() {
    int b = blockIdx.x, h = threadIdx.x;
    float c = 0.f;
    for (int i = 0; i < NCH; ++i) {
        int o = (b * NCH + i) * H + h;
        g_cf[o] = c;
        c = fmaf(g_A[o], c, g_Bf[o]);
    }
    c = 0.f;
    for (int i = NCH - 1; i >= 0; --i) {
        int o = (b * NCH + i) * H + h;
        g_cb[o] = c;
        c = fmaf(g_A[o], c, g_Bb[o]);
    }
}
__global__ void k_scan2() {
    int bc = blockIdx.x, h = threadIdx.x;
    size_t base = (size_t)bc * CL * H + h;
    float hf = g_cf[bc * H + h];
#pragma unroll 4
    for (int t = 0; t < CL; ++t) {
        size_t idx = base + (size_t)t * H;
        hf = fmaf(g_at[idx], hf, g_bt[idx]);
        g_hf[idx] = hf;
    }
    float hb = g_cb[bc * H + h];
#pragma unroll 4
    for (int t = CL - 1; t >= 0; --t) {
        size_t idx = base + (size_t)t * H;
        hb = fmaf(g_at[idx], hb, g_bt[idx]);
        g_hb[idx] = hb;
    }
}

// ---------------- K5: x1 = x + g1*([hf|hb] @ Wout + b) ----------------
__global__ __launch_bounds__(256, 1) void k_rout(const float* __restrict__ x,
                                                 const float* __restrict__ bout) {
    extern __shared__ char sm[];
    float* sBias = (float*)(sm + OFF_BIAS);
    float* sA = (float*)(sm + OFF_A);
    float* sB = (float*)(sm + OFF_B);
    int tid = threadIdx.x, wid = tid >> 5, lane = tid & 31;
    int wm = wid & 1, wn = wid >> 1, tr = lane >> 2, tc = lane & 3;
    int n0 = blockIdx.x * 128;
    int b = n0 >> 13;
    if (tid < 128) sBias[tid] = bout[tid];

    stage_act(sA, g_hf + (size_t)n0 * H, tid);
    cp_tileT(sB, g_WT[3], tid);
    __syncthreads();
    float acc[4][4][4];
    ZACC(acc);
    wgemm(sA, sB, acc, wm, wn, tr, tc);
    __syncthreads();
    stage_act(sA, g_hb + (size_t)n0 * H, tid);
    cp_tileT(sB, g_WT[4], tid);
    __syncthreads();
    wgemm(sA, sB, acc, wm, wn, tr, tc);

    float g1 = g_scal[b][2];
#pragma unroll
    for (int mt = 0; mt < 4; ++mt)
#pragma unroll
        for (int nt = 0; nt < 4; ++nt) {
            int r = wm * 64 + mt * 16 + tr, c = wn * 32 + nt * 8 + tc * 2;
            size_t o0 = (size_t)(n0 + r) * D + c, o1 = (size_t)(n0 + r + 8) * D + c;
            float2 x0 = *(const float2*)(x + o0);
            float2 x1v = *(const float2*)(x + o1);
            float2 w0, w1;
            w0.x = fmaf(g1, acc[mt][nt][0] + sBias[c],     x0.x);
            w0.y = fmaf(g1, acc[mt][nt][1] + sBias[c + 1], x0.y);
            w1.x = fmaf(g1, acc[mt][nt][2] + sBias[c],     x1v.x);
            w1.y = fmaf(g1, acc[mt][nt][3] + sBias[c + 1], x1v.y);
            *(float2*)(g_x1 + o0) = w0;
            *(float2*)(g_x1 + o1) = w1;
        }
}

// ---------------- K6: out = x1 + g2*(gelu(ln(x1)@W1+b1)@W2+b2) ----------------
__global__ __launch_bounds__(256, 1) void k_mlp(float* __restrict__ out,
                                                const float* __restrict__ b1m,
                                                const float* __restrict__ b2m) {
    extern __shared__ char sm[];
    float* sBias = (float*)(sm + OFF_BIAS);
    float* sA = (float*)(sm + OFF_A);
    float* sB = (float*)(sm + OFF_B);
    float* sC = (float*)(sm + OFF_C);
    int tid = threadIdx.x, wid = tid >> 5, lane = tid & 31;
    int wm = wid & 1, wn = wid >> 1, tr = lane >> 2, tc = lane & 3;
    int n0 = blockIdx.x * 128;
    int b = n0 >> 13;
    if (tid < 128) {
#pragma unroll
        for (int q = 0; q < 4; ++q) sBias[q * 128 + tid] = b1m[q * 128 + tid];
        sBias[512 + tid] = b2m[tid];
    }
    float s2p = 1.f + g_scal[b][3], b2s = g_scal[b][4], g2 = g_scal[b][5];

    for (int it = 0; it < 16; ++it) {
        int row = wid * 16 + it;
        const float* xp = g_x1 + (size_t)(n0 + row) * D;
        float v0 = xp[lane], v1 = xp[lane + 32], v2 = xp[lane + 64], v3 = xp[lane + 96];
        float m = warp_sum(v0 + v1 + v2 + v3) * (1.f / 128.f);
        float d0 = v0 - m, d1 = v1 - m, d2 = v2 - m, d3 = v3 - m;
        float rs = rsqrtf(warp_sum(d0*d0 + d1*d1 + d2*d2 + d3*d3) * (1.f / 128.f) + 1e-6f);
        float* ap = sA + row * STRIDE;
        ap[lane]      = to_tf32(fmaf(s2p, d0 * rs, b2s));
        ap[lane + 32] = to_tf32(fmaf(s2p, d1 * rs, b2s));
        ap[lane + 64] = to_tf32(fmaf(s2p, d2 * rs, b2s));
        ap[lane + 96] = to_tf32(fmaf(s2p, d3 * rs, b2s));
    }

    float macc[4][4][4];
    ZACC(macc);
    for (int cc = 0; cc < 4; ++cc) {
        cp_tileT(sB, g_WT[5 + cc], tid);
        __syncthreads();
        float tacc[4][4][4];
        ZACC(tacc);
        wgemm(sA, sB, tacc, wm, wn, tr, tc);
        __syncthreads();                    // done with sB (and prev sC reads)
#pragma unroll
        for (int mt = 0; mt < 4; ++mt)
#pragma unroll
            for (int nt = 0; nt < 4; ++nt) {
                int r = wm * 64 + mt * 16 + tr, c = wn * 32 + nt * 8 + tc * 2;
                sC[r * STRIDE + c]           = to_tf32(geluf_(tacc[mt][nt][0] + sBias[cc * 128 + c]));
                sC[r * STRIDE + c + 1]       = to_tf32(geluf_(tacc[mt][nt][1] + sBias[cc * 128 + c + 1]));
                sC[(r + 8) * STRIDE + c]     = to_tf32(geluf_(tacc[mt][nt][2] + sBias[cc * 128 + c]));
                sC[(r + 8) * STRIDE + c + 1] = to_tf32(geluf_(tacc[mt][nt][3] + sBias[cc * 128 + c + 1]));
            }
        cp_tileT(sB, g_WT[9 + cc], tid);
        __syncthreads();
        wgemm(sC, sB, macc, wm, wn, tr, tc);
        __syncthreads();                    // before next W1 overwrite of sB
    }

    float g2v = g2;
#pragma unroll
    for (int mt = 0; mt < 4; ++mt)
#pragma unroll
        for (int nt = 0; nt < 4; ++nt) {
            int r = wm * 64 + mt * 16 + tr, c = wn * 32 + nt * 8 + tc * 2;
            size_t o0 = (size_t)(n0 + r) * D + c, o1 = (size_t)(n0 + r + 8) * D + c;
            float2 x0 = *(const float2*)(g_x1 + o0);
            float2 x1v = *(const float2*)(g_x1 + o1);
            float2 w0, w1;
            w0.x = fmaf(g2v, macc[mt][nt][0] + sBias[512 + c],     x0.x);
            w0.y = fmaf(g2v, macc[mt][nt][1] + sBias[512 + c + 1], x0.y);
            w1.x = fmaf(g2v, macc[mt][nt][2] + sBias[512 + c],     x1v.x);
            w1.y = fmaf(g2v, macc[mt][nt][3] + sBias[512 + c + 1], x1v.y);
            *(float2*)(out + o0) = w0;
            *(float2*)(out + o1) = w1;
        }
}

// ---------------- launch ----------------
extern "C" void kernel_launch(void* const* d_in, const int* in_sizes, int n_in,
                              void* d_out, int out_size) {
    const float* x        = (const float*)d_in[0];
    const float* c        = (const float*)d_in[1];
    const float* cln1_sw  = (const float*)d_in[2];
    const float* cln1_sb  = (const float*)d_in[3];
    const float* cln1_bw  = (const float*)d_in[4];
    const float* cln1_bb  = (const float*)d_in[5];
    const float* gate1_w  = (const float*)d_in[6];
    const float* gate1_b  = (const float*)d_in[7];
    const float* rnn_in_w = (const float*)d_in[8];
    const float* rnn_in_b = (const float*)d_in[9];
    const float* pos_emb  = (const float*)d_in[10];
    const float* rnn_wi   = (const float*)d_in[11];
    const float* rnn_bi   = (const float*)d_in[12];
    const float* rnn_wr   = (const float*)d_in[13];
    const float* rnn_br   = (const float*)d_in[14];
    const float* rnn_a    = (const float*)d_in[15];
    const float* rnn_out_w= (const float*)d_in[16];
    const float* rnn_out_b= (const float*)d_in[17];
    const float* cln2_sw  = (const float*)d_in[18];
    const float* cln2_sb  = (const float*)d_in[19];
    const float* cln2_bw  = (const float*)d_in[20];
    const float* cln2_bb  = (const float*)d_in[21];
    const float* gate2_w  = (const float*)d_in[22];
    const float* gate2_b  = (const float*)d_in[23];
    const float* mlp_w1   = (const float*)d_in[24];
    const float* mlp_b1   = (const float*)d_in[25];
    const float* mlp_w2   = (const float*)d_in[26];
    const float* mlp_b2   = (const float*)d_in[27];
    float* out = (float*)d_out;

    cudaFuncSetAttribute(k_front, cudaFuncAttributeMaxDynamicSharedMemorySize, SMEM_SZ);
    cudaFuncSetAttribute(k_rout,  cudaFuncAttributeMaxDynamicSharedMemorySize, SMEM_SZ);
    cudaFuncSetAttribute(k_mlp,   cudaFuncAttributeMaxDynamicSharedMemorySize, SMEM_SZ);

    k_scal<<<1, 256>>>(c, cln1_sw, cln1_sb, cln1_bw, cln1_bb, gate1_w, gate1_b,
                       cln2_sw, cln2_sb, cln2_bw, cln2_bb, gate2_w, gate2_b, rnn_a);
    k_prep<<<13, 256>>>(rnn_in_w, rnn_wi, rnn_wr, rnn_out_w, mlp_w1, mlp_w2);
    k_front<<<NTOK / 128, 256, SMEM_SZ>>>(x, pos_emb, rnn_in_b, rnn_bi, rnn_br);
    k_scan1<<<BS * NCH, H>>>();
    k_carry<<<BS, H>>>();
    k_scan2<<<BS * NCH, H>>>();
    k_rout<<<NTOK / 128, 256, SMEM_SZ>>>(x, rnn_out_b);
    k_mlp<<<NTOK / 128, 256, SMEM_SZ>>>(out, mlp_b1, mlp_b2);
}

// round 8
// speedup vs baseline: 2.0059x; 1.1548x over previous
#include <cuda_runtime.h>
#include <math.h>
#include <stdint.h>

#define BS   8
#define LSEQ 8192
#define D    128
#define H    128
#define NTOK (BS * LSEQ)
#define CL   128
#define NCH  (LSEQ / CL)   // 64

#define STRIDE    132                       // floats per smem tile row
#define TILE_B    (128 * STRIDE * 4)        // 67584 bytes
#define OFF_BIAS  0
#define OFF_A     4096
#define OFF_B     (OFF_A + TILE_B)
#define OFF_C     (OFF_B + TILE_B)
#define SMEM_SZ   (OFF_C + TILE_B)          // 206848

// ---------------- device scratch ----------------
__device__ __align__(16) float g_scal[BS][6];
__device__ __align__(16) float g_loga[H];          // log2(a)
__device__ __align__(16) float g_WT[13][16384];    // transposed tf32 weights [n][k]
__device__ __align__(16) float g_at[(size_t)NTOK * H];
__device__ __align__(16) float g_bt[(size_t)NTOK * H];
__device__ __align__(16) float g_x1[(size_t)NTOK * D];
__device__ __align__(16) float g_A [BS * NCH * H];
__device__ __align__(16) float g_Bf[BS * NCH * H];
__device__ __align__(16) float g_Bb[BS * NCH * H];
__device__ __align__(16) float g_cf[BS * NCH * H];
__device__ __align__(16) float g_cb[BS * NCH * H];

// ---------------- helpers ----------------
__device__ __forceinline__ float to_tf32(float x) {
    uint32_t u;
    asm("cvt.rna.tf32.f32 %0, %1;" : "=r"(u) : "f"(x));
    return __uint_as_float(u);
}
__device__ __forceinline__ float fast_ex2(float x) { float y; asm("ex2.approx.f32 %0, %1;" : "=f"(y) : "f"(x)); return y; }
__device__ __forceinline__ float fast_rcp(float x) { float y; asm("rcp.approx.f32 %0, %1;" : "=f"(y) : "f"(x)); return y; }
__device__ __forceinline__ float sigf(float v) { return fast_rcp(1.f + fast_ex2(-1.4426950408889634f * v)); }
__device__ __forceinline__ float tanh_(float x) { return 1.f - 2.f * fast_rcp(1.f + fast_ex2(2.8853900817779268f * x)); }
__device__ __forceinline__ float geluf_(float v) {
    float v3 = v * v * v;
    return 0.5f * v * (1.f + tanh_(0.7978845608028654f * (v + 0.044715f * v3)));
}
__device__ __forceinline__ float warp_sum(float v) {
    v += __shfl_xor_sync(0xffffffffu, v, 16);
    v += __shfl_xor_sync(0xffffffffu, v, 8);
    v += __shfl_xor_sync(0xffffffffu, v, 4);
    v += __shfl_xor_sync(0xffffffffu, v, 2);
    v += __shfl_xor_sync(0xffffffffu, v, 1);
    return v;
}

#define MMA168(c, a, b0, b1)                                                        \
    asm volatile("mma.sync.aligned.m16n8k8.row.col.f32.tf32.tf32.f32 "              \
                 "{%0,%1,%2,%3}, {%4,%5,%6,%7}, {%8,%9}, {%0,%1,%2,%3};"            \
                 : "+f"((c)[0]), "+f"((c)[1]), "+f"((c)[2]), "+f"((c)[3])           \
                 : "r"((a)[0]), "r"((a)[1]), "r"((a)[2]), "r"((a)[3]),              \
                   "r"(b0), "r"(b1))

#define ZACC(a) do {                                                                \
    _Pragma("unroll") for (int _m = 0; _m < 2; ++_m)                                \
    _Pragma("unroll") for (int _n = 0; _n < 4; ++_n)                                \
    _Pragma("unroll") for (int _q = 0; _q < 4; ++_q) (a)[_m][_n][_q] = 0.f;         \
} while (0)

// warp GEMM: 32x32 patch of C(128x128) += A(128x128) * B^T stored [n][k]; 16 warps
__device__ __forceinline__ void wgemm(const float* __restrict__ sA,
                                      const float* __restrict__ sB,
                                      float (&acc)[2][4][4],
                                      int wm, int wn, int tr, int tc) {
#pragma unroll 4
    for (int ks = 0; ks < 16; ++ks) {
        int k0 = ks * 8;
        uint32_t a[2][4];
#pragma unroll
        for (int mt = 0; mt < 2; ++mt) {
            const float* ap = sA + (wm * 32 + mt * 16 + tr) * STRIDE + k0 + tc;
            a[mt][0] = __float_as_uint(ap[0]);
            a[mt][1] = __float_as_uint(ap[8 * STRIDE]);
            a[mt][2] = __float_as_uint(ap[4]);
            a[mt][3] = __float_as_uint(ap[8 * STRIDE + 4]);
        }
#pragma unroll
        for (int nt = 0; nt < 4; ++nt) {
            const float* bp = sB + (wn * 32 + nt * 8 + tr) * STRIDE + k0 + tc;
            uint32_t b0 = __float_as_uint(bp[0]);
            uint32_t b1 = __float_as_uint(bp[4]);
#pragma unroll
            for (int mt = 0; mt < 2; ++mt) MMA168(acc[mt][nt], a[mt], b0, b1);
        }
    }
}

// copy a prepared 128x128 tf32 tile (contiguous) into smem with STRIDE rows; 512 thr
__device__ __forceinline__ void cp_tileT(float* dst, const float* __restrict__ src, int tid) {
#pragma unroll
    for (int it = 0; it < 8; ++it) {
        int idx = tid + it * 512;              // float4 index
        int row = idx >> 5, j = idx & 31;
        *(float4*)(dst + row * STRIDE + j * 4) = ((const float4*)src)[idx];
    }
}
// copy a 128x128 fp32 activation tile (row-major, stride 128) into STRIDE smem; 512 thr
__device__ __forceinline__ void cp_act(float* dst, const float* __restrict__ g, int tid) {
#pragma unroll
    for (int it = 0; it < 8; ++it) {
        int idx = tid + it * 512;
        int row = idx >> 5, j4 = (idx & 31) << 2;
        *(float4*)(dst + row * STRIDE + j4) = *(const float4*)(g + (size_t)row * 128 + j4);
    }
}

// ---------------- K0: conditioning scalars + log2(a) ----------------
__global__ void k_scal(const float* __restrict__ c,
                       const float* sw1, const float* sb1, const float* bw1, const float* bb1,
                       const float* gw1, const float* gb1, const float* sw2, const float* sb2,
                       const float* bw2, const float* bb2, const float* gw2, const float* gb2,
                       const float* __restrict__ a) {
    int tid = threadIdx.x;
    if (tid < 48) {
        const float* ws[6] = {sw1, bw1, gw1, sw2, bw2, gw2};
        const float* bs[6] = {sb1, bb1, gb1, sb2, bb2, gb2};
        int b = tid / 6, j = tid % 6;
        float s = bs[j][0];
        const float* cp = c + b * 128;
        for (int k = 0; k < 128; ++k) s = fmaf(cp[k], ws[j][k], s);
        g_scal[b][j] = s;
    }
    int i = tid - 64;
    if (i >= 0 && i < H) g_loga[i] = log2f(a[i]);
}

// ---------------- K-prep: transposed tf32 weight tiles ----------------
// 0=Win 1=Wi 2=Wr 3=Wout(k<128) 4=Wout(k>=128) 5..8=W1 chunks 9..12=W2 chunks
__global__ void k_prep(const float* __restrict__ Win, const float* __restrict__ Wi,
                       const float* __restrict__ Wr, const float* __restrict__ Wout,
                       const float* __restrict__ W1, const float* __restrict__ W2) {
    int t = blockIdx.x, tid = threadIdx.x;
    for (int i = 0; i < 64; ++i) {
        int e = i * 256 + tid;
        int n = e >> 7, k = e & 127;
        float v;
        if (t == 0)      v = Win[k * 128 + n];
        else if (t == 1) v = Wi[k * 128 + n];
        else if (t == 2) v = Wr[k * 128 + n];
        else if (t == 3) v = Wout[k * 128 + n];
        else if (t == 4) v = Wout[(128 + k) * 128 + n];
        else if (t < 9)  v = W1[k * 512 + (t - 5) * 128 + n];
        else             v = W2[((t - 9) * 128 + k) * 128 + n];
        g_WT[t][n * 128 + k] = to_tf32(v);
    }
}

// ---------------- K1: x -> (at, bt) + chunk scan aggregates ----------------
__global__ __launch_bounds__(512, 1) void k_front(
    const float* __restrict__ x, const float* __restrict__ pos,
    const float* __restrict__ inb, const float* __restrict__ bi,
    const float* __restrict__ br) {
    extern __shared__ char sm[];
    float* sBias = (float*)(sm + OFF_BIAS);
    float* sA = (float*)(sm + OFF_A);
    float* sB = (float*)(sm + OFF_B);
    float* sC = (float*)(sm + OFF_C);
    int tid = threadIdx.x, wid = tid >> 5, lane = tid & 31;
    int wm = wid & 3, wn = wid >> 2, tr = lane >> 2, tc = lane & 3;
    int n0 = blockIdx.x * 128;
    int b = n0 >> 13, l0 = n0 & (LSEQ - 1);
    if (tid < 128) {
        sBias[tid] = inb[tid]; sBias[128 + tid] = bi[tid];
        sBias[256 + tid] = br[tid]; sBias[384 + tid] = g_loga[tid];
    }
    float s1p = 1.f + g_scal[b][0], b1s = g_scal[b][1];

    // conditioned double-LN -> tf32 A tile (16 warps x 8 rows)
#pragma unroll
    for (int it = 0; it < 8; ++it) {
        int row = wid * 8 + it;
        const float* xp = x + (size_t)(n0 + row) * D;
        float v0 = xp[lane], v1 = xp[lane + 32], v2 = xp[lane + 64], v3 = xp[lane + 96];
        float m = warp_sum(v0 + v1 + v2 + v3) * (1.f / 128.f);
        float d0 = v0 - m, d1 = v1 - m, d2 = v2 - m, d3 = v3 - m;
        float rs = rsqrtf(warp_sum(d0*d0 + d1*d1 + d2*d2 + d3*d3) * (1.f / 128.f) + 1e-6f);
        float h0 = fmaf(s1p, d0 * rs, b1s), h1 = fmaf(s1p, d1 * rs, b1s);
        float h2 = fmaf(s1p, d2 * rs, b1s), h3 = fmaf(s1p, d3 * rs, b1s);
        float m2 = warp_sum(h0 + h1 + h2 + h3) * (1.f / 128.f);
        float e0 = h0 - m2, e1 = h1 - m2, e2 = h2 - m2, e3 = h3 - m2;
        float rs2 = rsqrtf(warp_sum(e0*e0 + e1*e1 + e2*e2 + e3*e3) * (1.f / 128.f) + 1e-6f);
        float* ap = sA + row * STRIDE;
        ap[lane]      = to_tf32(e0 * rs2);
        ap[lane + 32] = to_tf32(e1 * rs2);
        ap[lane + 64] = to_tf32(e2 * rs2);
        ap[lane + 96] = to_tf32(e3 * rs2);
    }
    cp_tileT(sB, g_WT[0], tid);
    __syncthreads();

    float uacc[2][4][4];
    ZACC(uacc);
    wgemm(sA, sB, uacc, wm, wn, tr, tc);
    __syncthreads();                       // all warps done reading sA

    // u = gemm + bias + pos -> tf32 back into sA
#pragma unroll
    for (int mt = 0; mt < 2; ++mt)
#pragma unroll
        for (int nt = 0; nt < 4; ++nt) {
            int r = wm * 32 + mt * 16 + tr, c = wn * 32 + nt * 8 + tc * 2;
            float2 p0 = *(const float2*)(pos + (size_t)(l0 + r) * H + c);
            float2 p1 = *(const float2*)(pos + (size_t)(l0 + r + 8) * H + c);
            sA[r * STRIDE + c]           = to_tf32(uacc[mt][nt][0] + sBias[c]     + p0.x);
            sA[r * STRIDE + c + 1]       = to_tf32(uacc[mt][nt][1] + sBias[c + 1] + p0.y);
            sA[(r + 8) * STRIDE + c]     = to_tf32(uacc[mt][nt][2] + sBias[c]     + p1.x);
            sA[(r + 8) * STRIDE + c + 1] = to_tf32(uacc[mt][nt][3] + sBias[c + 1] + p1.y);
        }
    cp_tileT(sB, g_WT[1], tid);
    cp_tileT(sC, g_WT[2], tid);
    __syncthreads();

    float gacc[2][4][4];
    ZACC(gacc);
    wgemm(sA, sB, gacc, wm, wn, tr, tc);   // input gate pre-activation
#pragma unroll
    for (int mt = 0; mt < 2; ++mt)
#pragma unroll
        for (int nt = 0; nt < 4; ++nt) {
            int c = wn * 32 + nt * 8 + tc * 2;
            gacc[mt][nt][0] = sigf(gacc[mt][nt][0] + sBias[128 + c]);
            gacc[mt][nt][1] = sigf(gacc[mt][nt][1] + sBias[128 + c + 1]);
            gacc[mt][nt][2] = sigf(gacc[mt][nt][2] + sBias[128 + c]);
            gacc[mt][nt][3] = sigf(gacc[mt][nt][3] + sBias[128 + c + 1]);
        }
    float racc[2][4][4];
    ZACC(racc);
    wgemm(sA, sC, racc, wm, wn, tr, tc);   // recurrence gate pre-activation
    __syncthreads();                       // sB/sC free for at/bt staging

#pragma unroll
    for (int mt = 0; mt < 2; ++mt)
#pragma unroll
        for (int nt = 0; nt < 4; ++nt) {
            int r = wm * 32 + mt * 16 + tr, c = wn * 32 + nt * 8 + tc * 2;
            float2 u0 = *(const float2*)(sA + r * STRIDE + c);
            float2 u1 = *(const float2*)(sA + (r + 8) * STRIDE + c);
            float la0 = sBias[384 + c], la1 = sBias[384 + c + 1];
            float gr0 = sigf(racc[mt][nt][0] + sBias[256 + c]);
            float gr1 = sigf(racc[mt][nt][1] + sBias[256 + c + 1]);
            float gr2 = sigf(racc[mt][nt][2] + sBias[256 + c]);
            float gr3 = sigf(racc[mt][nt][3] + sBias[256 + c + 1]);
            float a0 = fast_ex2(8.f * gr0 * la0);
            float a1 = fast_ex2(8.f * gr1 * la1);
            float a2 = fast_ex2(8.f * gr2 * la0);
            float a3 = fast_ex2(8.f * gr3 * la1);
            float b0v = sqrtf(fmaxf(0.f, 1.f - a0 * a0)) * gacc[mt][nt][0] * u0.x;
            float b1v = sqrtf(fmaxf(0.f, 1.f - a1 * a1)) * gacc[mt][nt][1] * u0.y;
            float b2v = sqrtf(fmaxf(0.f, 1.f - a2 * a2)) * gacc[mt][nt][2] * u1.x;
            float b3v = sqrtf(fmaxf(0.f, 1.f - a3 * a3)) * gacc[mt][nt][3] * u1.y;
            size_t o0 = (size_t)(n0 + r) * H + c, o1 = (size_t)(n0 + r + 8) * H + c;
            *(float2*)(g_at + o0) = make_float2(a0, a1);
            *(float2*)(g_at + o1) = make_float2(a2, a3);
            *(float2*)(g_bt + o0) = make_float2(b0v, b1v);
            *(float2*)(g_bt + o1) = make_float2(b2v, b3v);
            // stage into smem for the chunk-local scan (fp32)
            *(float2*)(sB + r * STRIDE + c)       = make_float2(a0, a1);
            *(float2*)(sB + (r + 8) * STRIDE + c) = make_float2(a2, a3);
            *(float2*)(sC + r * STRIDE + c)       = make_float2(b0v, b1v);
            *(float2*)(sC + (r + 8) * STRIDE + c) = make_float2(b2v, b3v);
        }
    __syncthreads();

    // chunk-local scan aggregates (this CTA == chunk blockIdx.x)
    if (tid < 128) {
        int h = tid;
        float A = 1.f, hf = 0.f;
#pragma unroll 4
        for (int t = 0; t < CL; ++t) {
            float a = sB[t * STRIDE + h], bv = sC[t * STRIDE + h];
            A *= a;
            hf = fmaf(a, hf, bv);
        }
        float hb = 0.f;
#pragma unroll 4
        for (int t = CL - 1; t >= 0; --t)
            hb = fmaf(sB[t * STRIDE + h], hb, sC[t * STRIDE + h]);
        int o = blockIdx.x * H + h;
        g_A[o] = A; g_Bf[o] = hf; g_Bb[o] = hb;
    }
}

// ---------------- K3: cross-chunk carry scan ----------------
__global__ void k_carry() {
    int b = blockIdx.x, h = threadIdx.x;
    float c = 0.f;
    for (int i = 0; i < NCH; ++i) {
        int o = (b * NCH + i) * H + h;
        g_cf[o] = c;
        c = fmaf(g_A[o], c, g_Bf[o]);
    }
    c = 0.f;
    for (int i = NCH - 1; i >= 0; --i) {
        int o = (b * NCH + i) * H + h;
        g_cb[o] = c;
        c = fmaf(g_A[o], c, g_Bb[o]);
    }
}

// ---------------- K5: in-kernel scan2 + x1 = x + g1*([hf|hb] @ Wout + b) ----------------
__global__ __launch_bounds__(512, 1) void k_rout(const float* __restrict__ x,
                                                 const float* __restrict__ bout) {
    extern __shared__ char sm[];
    float* sBias = (float*)(sm + OFF_BIAS);
    float* sA = (float*)(sm + OFF_A);
    float* sB = (float*)(sm + OFF_B);
    float* sC = (float*)(sm + OFF_C);
    int tid = threadIdx.x, wid = tid >> 5, lane = tid & 31;
    int wm = wid & 3, wn = wid >> 2, tr = lane >> 2, tc = lane & 3;
    int n0 = blockIdx.x * 128;
    int b = n0 >> 13;
    int bc = blockIdx.x;                   // chunk index
    if (tid < 128) sBias[tid] = bout[tid];

    cp_act(sA, g_at + (size_t)n0 * H, tid);        // at (fp32)
    cp_act(sC, g_bt + (size_t)n0 * H, tid);        // bt (fp32)
    cp_tileT(sB, g_WT[3], tid);
    __syncthreads();

    // forward scan: overwrite sC with tf32 hf
    if (tid < 128) {
        int h = tid;
        float hf = g_cf[bc * H + h];
#pragma unroll 4
        for (int t = 0; t < CL; ++t) {
            hf = fmaf(sA[t * STRIDE + h], hf, sC[t * STRIDE + h]);
            sC[t * STRIDE + h] = to_tf32(hf);
        }
    }
    __syncthreads();
    float acc[2][4][4];
    ZACC(acc);
    wgemm(sC, sB, acc, wm, wn, tr, tc);
    __syncthreads();                       // done reading sC / sB

    cp_act(sC, g_bt + (size_t)n0 * H, tid);        // reload bt
    cp_tileT(sB, g_WT[4], tid);
    __syncthreads();

    // backward scan: overwrite sC with tf32 hb
    if (tid < 128) {
        int h = tid;
        float hb = g_cb[bc * H + h];
#pragma unroll 4
        for (int t = CL - 1; t >= 0; --t) {
            hb = fmaf(sA[t * STRIDE + h], hb, sC[t * STRIDE + h]);
            sC[t * STRIDE + h] = to_tf32(hb);
        }
    }
    __syncthreads();
    wgemm(sC, sB, acc, wm, wn, tr, tc);

    float g1 = g_scal[b][2];
#pragma unroll
    for (int mt = 0; mt < 2; ++mt)
#pragma unroll
        for (int nt = 0; nt < 4; ++nt) {
            int r = wm * 32 + mt * 16 + tr, c = wn * 32 + nt * 8 + tc * 2;
            size_t o0 = (size_t)(n0 + r) * D + c, o1 = (size_t)(n0 + r + 8) * D + c;
            float2 x0 = *(const float2*)(x + o0);
            float2 x1v = *(const float2*)(x + o1);
            float2 w0, w1;
            w0.x = fmaf(g1, acc[mt][nt][0] + sBias[c],     x0.x);
            w0.y = fmaf(g1, acc[mt][nt][1] + sBias[c + 1], x0.y);
            w1.x = fmaf(g1, acc[mt][nt][2] + sBias[c],     x1v.x);
            w1.y = fmaf(g1, acc[mt][nt][3] + sBias[c + 1], x1v.y);
            *(float2*)(g_x1 + o0) = w0;
            *(float2*)(g_x1 + o1) = w1;
        }
}

// ---------------- K6: out = x1 + g2*(gelu(ln(x1)@W1+b1)@W2+b2) ----------------
__global__ __launch_bounds__(512, 1) void k_mlp(float* __restrict__ out,
                                                const float* __restrict__ b1m,
                                                const float* __restrict__ b2m) {
    extern __shared__ char sm[];
    float* sBias = (float*)(sm + OFF_BIAS);
    float* sA = (float*)(sm + OFF_A);
    float* sB = (float*)(sm + OFF_B);
    float* sC = (float*)(sm + OFF_C);
    int tid = threadIdx.x, wid = tid >> 5, lane = tid & 31;
    int wm = wid & 3, wn = wid >> 2, tr = lane >> 2, tc = lane & 3;
    int n0 = blockIdx.x * 128;
    int b = n0 >> 13;
    if (tid < 128) {
#pragma unroll
        for (int q = 0; q < 4; ++q) sBias[q * 128 + tid] = b1m[q * 128 + tid];
        sBias[512 + tid] = b2m[tid];
    }
    float s2p = 1.f + g_scal[b][3], b2s = g_scal[b][4], g2 = g_scal[b][5];

#pragma unroll
    for (int it = 0; it < 8; ++it) {
        int row = wid * 8 + it;
        const float* xp = g_x1 + (size_t)(n0 + row) * D;
        float v0 = xp[lane], v1 = xp[lane + 32], v2 = xp[lane + 64], v3 = xp[lane + 96];
        float m = warp_sum(v0 + v1 + v2 + v3) * (1.f / 128.f);
        float d0 = v0 - m, d1 = v1 - m, d2 = v2 - m, d3 = v3 - m;
        float rs = rsqrtf(warp_sum(d0*d0 + d1*d1 + d2*d2 + d3*d3) * (1.f / 128.f) + 1e-6f);
        float* ap = sA + row * STRIDE;
        ap[lane]      = to_tf32(fmaf(s2p, d0 * rs, b2s));
        ap[lane + 32] = to_tf32(fmaf(s2p, d1 * rs, b2s));
        ap[lane + 64] = to_tf32(fmaf(s2p, d2 * rs, b2s));
        ap[lane + 96] = to_tf32(fmaf(s2p, d3 * rs, b2s));
    }

    float macc[2][4][4];
    ZACC(macc);
    for (int cc = 0; cc < 4; ++cc) {
        cp_tileT(sB, g_WT[5 + cc], tid);
        __syncthreads();
        float tacc[2][4][4];
        ZACC(tacc);
        wgemm(sA, sB, tacc, wm, wn, tr, tc);
        __syncthreads();                    // done with sB (and prev sC reads)
#pragma unroll
        for (int mt = 0; mt < 2; ++mt)
#pragma unroll
            for (int nt = 0; nt < 4; ++nt) {
                int r = wm * 32 + mt * 16 + tr, c = wn * 32 + nt * 8 + tc * 2;
                sC[r * STRIDE + c]           = to_tf32(geluf_(tacc[mt][nt][0] + sBias[cc * 128 + c]));
                sC[r * STRIDE + c + 1]       = to_tf32(geluf_(tacc[mt][nt][1] + sBias[cc * 128 + c + 1]));
                sC[(r + 8) * STRIDE + c]     = to_tf32(geluf_(tacc[mt][nt][2] + sBias[cc * 128 + c]));
                sC[(r + 8) * STRIDE + c + 1] = to_tf32(geluf_(tacc[mt][nt][3] + sBias[cc * 128 + c + 1]));
            }
        cp_tileT(sB, g_WT[9 + cc], tid);
        __syncthreads();
        wgemm(sC, sB, macc, wm, wn, tr, tc);
        __syncthreads();                    // before next W1 overwrite of sB
    }

#pragma unroll
    for (int mt = 0; mt < 2; ++mt)
#pragma unroll
        for (int nt = 0; nt < 4; ++nt) {
            int r = wm * 32 + mt * 16 + tr, c = wn * 32 + nt * 8 + tc * 2;
            size_t o0 = (size_t)(n0 + r) * D + c, o1 = (size_t)(n0 + r + 8) * D + c;
            float2 x0 = *(const float2*)(g_x1 + o0);
            float2 x1v = *(const float2*)(g_x1 + o1);
            float2 w0, w1;
            w0.x = fmaf(g2, macc[mt][nt][0] + sBias[512 + c],     x0.x);
            w0.y = fmaf(g2, macc[mt][nt][1] + sBias[512 + c + 1], x0.y);
            w1.x = fmaf(g2, macc[mt][nt][2] + sBias[512 + c],     x1v.x);
            w1.y = fmaf(g2, macc[mt][nt][3] + sBias[512 + c + 1], x1v.y);
            *(float2*)(out + o0) = w0;
            *(float2*)(out + o1) = w1;
        }
}

// ---------------- launch ----------------
extern "C" void kernel_launch(void* const* d_in, const int* in_sizes, int n_in,
                              void* d_out, int out_size) {
    const float* x        = (const float*)d_in[0];
    const float* c        = (const float*)d_in[1];
    const float* cln1_sw  = (const float*)d_in[2];
    const float* cln1_sb  = (const float*)d_in[3];
    const float* cln1_bw  = (const float*)d_in[4];
    const float* cln1_bb  = (const float*)d_in[5];
    const float* gate1_w  = (const float*)d_in[6];
    const float* gate1_b  = (const float*)d_in[7];
    const float* rnn_in_w = (const float*)d_in[8];
    const float* rnn_in_b = (const float*)d_in[9];
    const float* pos_emb  = (const float*)d_in[10];
    const float* rnn_wi   = (const float*)d_in[11];
    const float* rnn_bi   = (const float*)d_in[12];
    const float* rnn_wr   = (const float*)d_in[13];
    const float* rnn_br   = (const float*)d_in[14];
    const float* rnn_a    = (const float*)d_in[15];
    const float* rnn_out_w= (const float*)d_in[16];
    const float* rnn_out_b= (const float*)d_in[17];
    const float* cln2_sw  = (const float*)d_in[18];
    const float* cln2_sb  = (const float*)d_in[19];
    const float* cln2_bw  = (const float*)d_in[20];
    const float* cln2_bb  = (const float*)d_in[21];
    const float* gate2_w  = (const float*)d_in[22];
    const float* gate2_b  = (const float*)d_in[23];
    const float* mlp_w1   = (const float*)d_in[24];
    const float* mlp_b1   = (const float*)d_in[25];
    const float* mlp_w2   = (const float*)d_in[26];
    const float* mlp_b2   = (const float*)d_in[27];
    float* out = (float*)d_out;

    cudaFuncSetAttribute(k_front, cudaFuncAttributeMaxDynamicSharedMemorySize, SMEM_SZ);
    cudaFuncSetAttribute(k_rout,  cudaFuncAttributeMaxDynamicSharedMemorySize, SMEM_SZ);
    cudaFuncSetAttribute(k_mlp,   cudaFuncAttributeMaxDynamicSharedMemorySize, SMEM_SZ);

    k_scal<<<1, 256>>>(c, cln1_sw, cln1_sb, cln1_bw, cln1_bb, gate1_w, gate1_b,
                       cln2_sw, cln2_sb, cln2_bw, cln2_bb, gate2_w, gate2_b, rnn_a);
    k_prep<<<13, 256>>>(rnn_in_w, rnn_wi, rnn_wr, rnn_out_w, mlp_w1, mlp_w2);
    k_front<<<NTOK / 128, 512, SMEM_SZ>>>(x, pos_emb, rnn_in_b, rnn_bi, rnn_br);
    k_carry<<<BS, H>>>();
    k_rout<<<NTOK / 128, 512, SMEM_SZ>>>(x, rnn_out_b);
    k_mlp<<<NTOK / 128, 512, SMEM_SZ>>>(out, mlp_b1, mlp_b2);
}

// round 9
// speedup vs baseline: 3.1440x; 1.5673x over previous
#include <cuda_runtime.h>
#include <math.h>
#include <stdint.h>

#define BS   8
#define LSEQ 8192
#define D    128
#define H    128
#define NTOK (BS * LSEQ)
#define CL   128
#define NCH  (LSEQ / CL)   // 64

#define STRIDE    132                       // floats per smem tile row
#define TILE_B    (128 * STRIDE * 4)        // 67584 bytes
#define OFF_BIAS  0
#define OFF_A     4096
#define OFF_B     (OFF_A + TILE_B)
#define OFF_C     (OFF_B + TILE_B)
#define SMEM_SZ   (OFF_C + TILE_B)          // 206848

// ---------------- device scratch ----------------
__device__ __align__(16) float g_scal[BS][6];
__device__ __align__(16) float g_loga[H];          // log2(a)
__device__ __align__(16) float g_WT[13][16384];    // transposed tf32 weights [n][k]
__device__ __align__(16) float g_at[(size_t)NTOK * H];
__device__ __align__(16) float g_bt[(size_t)NTOK * H];
__device__ __align__(16) float g_x1[(size_t)NTOK * D];
__device__ __align__(16) float g_A [BS * NCH * H];
__device__ __align__(16) float g_Bf[BS * NCH * H];
__device__ __align__(16) float g_Bb[BS * NCH * H];

// ---------------- helpers ----------------
__device__ __forceinline__ float to_tf32(float x) {
    uint32_t u;
    asm("cvt.rna.tf32.f32 %0, %1;" : "=r"(u) : "f"(x));
    return __uint_as_float(u);
}
__device__ __forceinline__ float fast_ex2(float x) { float y; asm("ex2.approx.f32 %0, %1;" : "=f"(y) : "f"(x)); return y; }
__device__ __forceinline__ float fast_rcp(float x) { float y; asm("rcp.approx.f32 %0, %1;" : "=f"(y) : "f"(x)); return y; }
__device__ __forceinline__ float sigf(float v) { return fast_rcp(1.f + fast_ex2(-1.4426950408889634f * v)); }
__device__ __forceinline__ float tanh_(float x) { return 1.f - 2.f * fast_rcp(1.f + fast_ex2(2.8853900817779268f * x)); }
__device__ __forceinline__ float geluf_(float v) {
    float v3 = v * v * v;
    return 0.5f * v * (1.f + tanh_(0.7978845608028654f * (v + 0.044715f * v3)));
}
__device__ __forceinline__ float warp_sum(float v) {
    v += __shfl_xor_sync(0xffffffffu, v, 16);
    v += __shfl_xor_sync(0xffffffffu, v, 8);
    v += __shfl_xor_sync(0xffffffffu, v, 4);
    v += __shfl_xor_sync(0xffffffffu, v, 2);
    v += __shfl_xor_sync(0xffffffffu, v, 1);
    return v;
}

#define MMA168(c, a, b0, b1)                                                        \
    asm volatile("mma.sync.aligned.m16n8k8.row.col.f32.tf32.tf32.f32 "              \
                 "{%0,%1,%2,%3}, {%4,%5,%6,%7}, {%8,%9}, {%0,%1,%2,%3};"            \
                 : "+f"((c)[0]), "+f"((c)[1]), "+f"((c)[2]), "+f"((c)[3])           \
                 : "r"((a)[0]), "r"((a)[1]), "r"((a)[2]), "r"((a)[3]),              \
                   "r"(b0), "r"(b1))

#define ZACC(a) do {                                                                \
    _Pragma("unroll") for (int _m = 0; _m < 2; ++_m)                                \
    _Pragma("unroll") for (int _n = 0; _n < 4; ++_n)                                \
    _Pragma("unroll") for (int _q = 0; _q < 4; ++_q) (a)[_m][_n][_q] = 0.f;         \
} while (0)

// warp GEMM: 32x32 patch of C(128x128) += A(128x128) * B^T stored [n][k]; 16 warps
__device__ __forceinline__ void wgemm(const float* __restrict__ sA,
                                      const float* __restrict__ sB,
                                      float (&acc)[2][4][4],
                                      int wm, int wn, int tr, int tc) {
#pragma unroll 4
    for (int ks = 0; ks < 16; ++ks) {
        int k0 = ks * 8;
        uint32_t a[2][4];
#pragma unroll
        for (int mt = 0; mt < 2; ++mt) {
            const float* ap = sA + (wm * 32 + mt * 16 + tr) * STRIDE + k0 + tc;
            a[mt][0] = __float_as_uint(ap[0]);
            a[mt][1] = __float_as_uint(ap[8 * STRIDE]);
            a[mt][2] = __float_as_uint(ap[4]);
            a[mt][3] = __float_as_uint(ap[8 * STRIDE + 4]);
        }
#pragma unroll
        for (int nt = 0; nt < 4; ++nt) {
            const float* bp = sB + (wn * 32 + nt * 8 + tr) * STRIDE + k0 + tc;
            uint32_t b0 = __float_as_uint(bp[0]);
            uint32_t b1 = __float_as_uint(bp[4]);
#pragma unroll
            for (int mt = 0; mt < 2; ++mt) MMA168(acc[mt][nt], a[mt], b0, b1);
        }
    }
}

// copy a prepared 128x128 tf32 tile (contiguous) into smem with STRIDE rows
__device__ __forceinline__ void cp_tileT(float* dst, const float* __restrict__ src, int tid) {
#pragma unroll
    for (int it = 0; it < 8; ++it) {
        int idx = tid + it * 512;              // float4 index
        int row = idx >> 5, j = idx & 31;
        *(float4*)(dst + row * STRIDE + j * 4) = ((const float4*)src)[idx];
    }
}
// same, generic thread range
__device__ __forceinline__ void cp_tileT_n(float* dst, const float* __restrict__ src,
                                           int t, int nthr) {
    for (int idx = t; idx < 4096; idx += nthr) {
        int row = idx >> 5, j = idx & 31;
        *(float4*)(dst + row * STRIDE + j * 4) = ((const float4*)src)[idx];
    }
}
// copy a 128x128 fp32 activation tile (row-major, stride 128) into STRIDE smem
__device__ __forceinline__ void cp_act(float* dst, const float* __restrict__ g, int tid) {
#pragma unroll
    for (int it = 0; it < 8; ++it) {
        int idx = tid + it * 512;
        int row = idx >> 5, j4 = (idx & 31) << 2;
        *(float4*)(dst + row * STRIDE + j4) = *(const float4*)(g + (size_t)row * 128 + j4);
    }
}
__device__ __forceinline__ void cp_act_n(float* dst, const float* __restrict__ g,
                                         int t, int nthr) {
    for (int idx = t; idx < 4096; idx += nthr) {
        int row = idx >> 5, j4 = (idx & 31) << 2;
        *(float4*)(dst + row * STRIDE + j4) = *(const float4*)(g + (size_t)row * 128 + j4);
    }
}

// ---------------- K0: conditioning scalars + log2(a) ----------------
__global__ void k_scal(const float* __restrict__ c,
                       const float* sw1, const float* sb1, const float* bw1, const float* bb1,
                       const float* gw1, const float* gb1, const float* sw2, const float* sb2,
                       const float* bw2, const float* bb2, const float* gw2, const float* gb2,
                       const float* __restrict__ a) {
    int tid = threadIdx.x;
    if (tid < 48) {
        const float* ws[6] = {sw1, bw1, gw1, sw2, bw2, gw2};
        const float* bs[6] = {sb1, bb1, gb1, sb2, bb2, gb2};
        int b = tid / 6, j = tid % 6;
        float s = bs[j][0];
        const float* cp = c + b * 128;
        for (int k = 0; k < 128; ++k) s = fmaf(cp[k], ws[j][k], s);
        g_scal[b][j] = s;
    }
    int i = tid - 64;
    if (i >= 0 && i < H) g_loga[i] = log2f(a[i]);
}

// ---------------- K-prep: transposed tf32 weight tiles (52 blocks) ----------------
// tile t = bid>>2: 0=Win 1=Wi 2=Wr 3=Wout(k<128) 4=Wout(k>=128) 5..8=W1 9..12=W2
__global__ void k_prep(const float* __restrict__ Win, const float* __restrict__ Wi,
                       const float* __restrict__ Wr, const float* __restrict__ Wout,
                       const float* __restrict__ W1, const float* __restrict__ W2) {
    int t = blockIdx.x >> 2, quarter = blockIdx.x & 3, tid = threadIdx.x;
    for (int i = quarter * 16; i < quarter * 16 + 16; ++i) {
        int e = i * 256 + tid;
        int n = e >> 7, k = e & 127;
        float v;
        if (t == 0)      v = Win[k * 128 + n];
        else if (t == 1) v = Wi[k * 128 + n];
        else if (t == 2) v = Wr[k * 128 + n];
        else if (t == 3) v = Wout[k * 128 + n];
        else if (t == 4) v = Wout[(128 + k) * 128 + n];
        else if (t < 9)  v = W1[k * 512 + (t - 5) * 128 + n];
        else             v = W2[((t - 9) * 128 + k) * 128 + n];
        g_WT[t][n * 128 + k] = to_tf32(v);
    }
}

// ---------------- K1: x -> (at, bt) + chunk scan aggregates ----------------
__global__ __launch_bounds__(512, 1) void k_front(
    const float* __restrict__ x, const float* __restrict__ pos,
    const float* __restrict__ inb, const float* __restrict__ bi,
    const float* __restrict__ br) {
    extern __shared__ char sm[];
    float* sBias = (float*)(sm + OFF_BIAS);
    float* sA = (float*)(sm + OFF_A);
    float* sB = (float*)(sm + OFF_B);
    float* sC = (float*)(sm + OFF_C);
    int tid = threadIdx.x, wid = tid >> 5, lane = tid & 31;
    int wm = wid & 3, wn = wid >> 2, tr = lane >> 2, tc = lane & 3;
    int n0 = blockIdx.x * 128;
    int b = n0 >> 13, l0 = n0 & (LSEQ - 1);
    if (tid < 128) {
        sBias[tid] = inb[tid]; sBias[128 + tid] = bi[tid];
        sBias[256 + tid] = br[tid]; sBias[384 + tid] = g_loga[tid];
    }
    float s1p = 1.f + g_scal[b][0], b1s = g_scal[b][1];

    // conditioned double-LN -> tf32 A tile (16 warps x 8 rows)
#pragma unroll
    for (int it = 0; it < 8; ++it) {
        int row = wid * 8 + it;
        const float* xp = x + (size_t)(n0 + row) * D;
        float v0 = xp[lane], v1 = xp[lane + 32], v2 = xp[lane + 64], v3 = xp[lane + 96];
        float m = warp_sum(v0 + v1 + v2 + v3) * (1.f / 128.f);
        float d0 = v0 - m, d1 = v1 - m, d2 = v2 - m, d3 = v3 - m;
        float rs = rsqrtf(warp_sum(d0*d0 + d1*d1 + d2*d2 + d3*d3) * (1.f / 128.f) + 1e-6f);
        float h0 = fmaf(s1p, d0 * rs, b1s), h1 = fmaf(s1p, d1 * rs, b1s);
        float h2 = fmaf(s1p, d2 * rs, b1s), h3 = fmaf(s1p, d3 * rs, b1s);
        float m2 = warp_sum(h0 + h1 + h2 + h3) * (1.f / 128.f);
        float e0 = h0 - m2, e1 = h1 - m2, e2 = h2 - m2, e3 = h3 - m2;
        float rs2 = rsqrtf(warp_sum(e0*e0 + e1*e1 + e2*e2 + e3*e3) * (1.f / 128.f) + 1e-6f);
        float* ap = sA + row * STRIDE;
        ap[lane]      = to_tf32(e0 * rs2);
        ap[lane + 32] = to_tf32(e1 * rs2);
        ap[lane + 64] = to_tf32(e2 * rs2);
        ap[lane + 96] = to_tf32(e3 * rs2);
    }
    cp_tileT(sB, g_WT[0], tid);
    __syncthreads();

    float uacc[2][4][4];
    ZACC(uacc);
    wgemm(sA, sB, uacc, wm, wn, tr, tc);
    __syncthreads();                       // all warps done reading sA

    // u = gemm + bias + pos -> tf32 back into sA
#pragma unroll
    for (int mt = 0; mt < 2; ++mt)
#pragma unroll
        for (int nt = 0; nt < 4; ++nt) {
            int r = wm * 32 + mt * 16 + tr, c = wn * 32 + nt * 8 + tc * 2;
            float2 p0 = *(const float2*)(pos + (size_t)(l0 + r) * H + c);
            float2 p1 = *(const float2*)(pos + (size_t)(l0 + r + 8) * H + c);
            sA[r * STRIDE + c]           = to_tf32(uacc[mt][nt][0] + sBias[c]     + p0.x);
            sA[r * STRIDE + c + 1]       = to_tf32(uacc[mt][nt][1] + sBias[c + 1] + p0.y);
            sA[(r + 8) * STRIDE + c]     = to_tf32(uacc[mt][nt][2] + sBias[c]     + p1.x);
            sA[(r + 8) * STRIDE + c + 1] = to_tf32(uacc[mt][nt][3] + sBias[c + 1] + p1.y);
        }
    cp_tileT(sB, g_WT[1], tid);
    cp_tileT(sC, g_WT[2], tid);
    __syncthreads();

    float gacc[2][4][4];
    ZACC(gacc);
    wgemm(sA, sB, gacc, wm, wn, tr, tc);   // input gate pre-activation
#pragma unroll
    for (int mt = 0; mt < 2; ++mt)
#pragma unroll
        for (int nt = 0; nt < 4; ++nt) {
            int c = wn * 32 + nt * 8 + tc * 2;
            gacc[mt][nt][0] = sigf(gacc[mt][nt][0] + sBias[128 + c]);
            gacc[mt][nt][1] = sigf(gacc[mt][nt][1] + sBias[128 + c + 1]);
            gacc[mt][nt][2] = sigf(gacc[mt][nt][2] + sBias[128 + c]);
            gacc[mt][nt][3] = sigf(gacc[mt][nt][3] + sBias[128 + c + 1]);
        }
    float racc[2][4][4];
    ZACC(racc);
    wgemm(sA, sC, racc, wm, wn, tr, tc);   // recurrence gate pre-activation
    __syncthreads();                       // sB/sC free for at/bt staging

#pragma unroll
    for (int mt = 0; mt < 2; ++mt)
#pragma unroll
        for (int nt = 0; nt < 4; ++nt) {
            int r = wm * 32 + mt * 16 + tr, c = wn * 32 + nt * 8 + tc * 2;
            float2 u0 = *(const float2*)(sA + r * STRIDE + c);
            float2 u1 = *(const float2*)(sA + (r + 8) * STRIDE + c);
            float la0 = sBias[384 + c], la1 = sBias[384 + c + 1];
            float gr0 = sigf(racc[mt][nt][0] + sBias[256 + c]);
            float gr1 = sigf(racc[mt][nt][1] + sBias[256 + c + 1]);
            float gr2 = sigf(racc[mt][nt][2] + sBias[256 + c]);
            float gr3 = sigf(racc[mt][nt][3] + sBias[256 + c + 1]);
            float a0 = fast_ex2(8.f * gr0 * la0);
            float a1 = fast_ex2(8.f * gr1 * la1);
            float a2 = fast_ex2(8.f * gr2 * la0);
            float a3 = fast_ex2(8.f * gr3 * la1);
            float b0v = sqrtf(fmaxf(0.f, 1.f - a0 * a0)) * gacc[mt][nt][0] * u0.x;
            float b1v = sqrtf(fmaxf(0.f, 1.f - a1 * a1)) * gacc[mt][nt][1] * u0.y;
            float b2v = sqrtf(fmaxf(0.f, 1.f - a2 * a2)) * gacc[mt][nt][2] * u1.x;
            float b3v = sqrtf(fmaxf(0.f, 1.f - a3 * a3)) * gacc[mt][nt][3] * u1.y;
            size_t o0 = (size_t)(n0 + r) * H + c, o1 = (size_t)(n0 + r + 8) * H + c;
            *(float2*)(g_at + o0) = make_float2(a0, a1);
            *(float2*)(g_at + o1) = make_float2(a2, a3);
            *(float2*)(g_bt + o0) = make_float2(b0v, b1v);
            *(float2*)(g_bt + o1) = make_float2(b2v, b3v);
            // stage into smem for the chunk-local scan (fp32)
            *(float2*)(sB + r * STRIDE + c)       = make_float2(a0, a1);
            *(float2*)(sB + (r + 8) * STRIDE + c) = make_float2(a2, a3);
            *(float2*)(sC + r * STRIDE + c)       = make_float2(b0v, b1v);
            *(float2*)(sC + (r + 8) * STRIDE + c) = make_float2(b2v, b3v);
        }
    __syncthreads();

    // chunk-local scan aggregates (this CTA == chunk blockIdx.x)
    if (tid < 128) {
        int h = tid;
        float A = 1.f, hf = 0.f;
#pragma unroll 4
        for (int t = 0; t < CL; ++t) {
            float a = sB[t * STRIDE + h], bv = sC[t * STRIDE + h];
            A *= a;
            hf = fmaf(a, hf, bv);
        }
        float hb = 0.f;
#pragma unroll 4
        for (int t = CL - 1; t >= 0; --t)
            hb = fmaf(sB[t * STRIDE + h], hb, sC[t * STRIDE + h]);
        int o = blockIdx.x * H + h;
        g_A[o] = A; g_Bf[o] = hf; g_Bb[o] = hb;
    }
}

// ---------------- K5: per-CTA carry + scan + x1 = x + g1*([hf|hb]@Wout + b) ----------------
__global__ __launch_bounds__(512, 1) void k_rout(const float* __restrict__ x,
                                                 const float* __restrict__ bout) {
    extern __shared__ char sm[];
    float* sBias = (float*)(sm + OFF_BIAS);
    float* sA = (float*)(sm + OFF_A);
    float* sB = (float*)(sm + OFF_B);
    float* sC = (float*)(sm + OFF_C);
    int tid = threadIdx.x, wid = tid >> 5, lane = tid & 31;
    int wm = wid & 3, wn = wid >> 2, tr = lane >> 2, tc = lane & 3;
    int n0 = blockIdx.x * 128;
    int b = n0 >> 13;
    int bc = blockIdx.x;
    int bchunk = bc & (NCH - 1);           // chunk index within sequence
    int cbase = bc - bchunk;               // first chunk of this batch

    float cf = 0.f, cb = 0.f;
    if (tid < 128) {
        // compute this chunk's forward/backward carries from published aggregates
        sBias[tid] = bout[tid];
        int h = tid;
        for (int i0 = 0; i0 < bchunk; i0 += 8) {
            float a[8], bf[8];
#pragma unroll
            for (int j = 0; j < 8; ++j) {
                int i = i0 + j;
                bool v = i < bchunk;
                int idx = (cbase + (v ? i : 0)) * H + h;
                a[j]  = v ? g_A[idx]  : 1.f;
                bf[j] = v ? g_Bf[idx] : 0.f;
            }
#pragma unroll
            for (int j = 0; j < 8; ++j) cf = fmaf(a[j], cf, bf[j]);
        }
        for (int i0 = NCH - 1; i0 > bchunk; i0 -= 8) {
            float a[8], bb_[8];
#pragma unroll
            for (int j = 0; j < 8; ++j) {
                int i = i0 - j;
                bool v = i > bchunk;
                int idx = (cbase + (v ? i : 0)) * H + h;
                a[j]   = v ? g_A[idx]  : 1.f;
                bb_[j] = v ? g_Bb[idx] : 0.f;
            }
#pragma unroll
            for (int j = 0; j < 8; ++j) cb = fmaf(a[j], cb, bb_[j]);
        }
    } else {
        int t = tid - 128;
        cp_act_n(sA, g_at + (size_t)n0 * H, t, 384);   // at (fp32)
        cp_act_n(sC, g_bt + (size_t)n0 * H, t, 384);   // bt (fp32)
        cp_tileT_n(sB, g_WT[3], t, 384);
    }
    __syncthreads();

    // forward scan: overwrite sC with tf32 hf
    if (tid < 128) {
        int h = tid;
        float hf = cf;
#pragma unroll 4
        for (int t = 0; t < CL; ++t) {
            hf = fmaf(sA[t * STRIDE + h], hf, sC[t * STRIDE + h]);
            sC[t * STRIDE + h] = to_tf32(hf);
        }
    }
    __syncthreads();
    float acc[2][4][4];
    ZACC(acc);
    wgemm(sC, sB, acc, wm, wn, tr, tc);
    __syncthreads();                       // done reading sC / sB

    cp_act(sC, g_bt + (size_t)n0 * H, tid);        // reload bt
    cp_tileT(sB, g_WT[4], tid);
    __syncthreads();

    // backward scan: overwrite sC with tf32 hb
    if (tid < 128) {
        int h = tid;
        float hb = cb;
#pragma unroll 4
        for (int t = CL - 1; t >= 0; --t) {
            hb = fmaf(sA[t * STRIDE + h], hb, sC[t * STRIDE + h]);
            sC[t * STRIDE + h] = to_tf32(hb);
        }
    }
    __syncthreads();
    wgemm(sC, sB, acc, wm, wn, tr, tc);

    float g1 = g_scal[b][2];
#pragma unroll
    for (int mt = 0; mt < 2; ++mt)
#pragma unroll
        for (int nt = 0; nt < 4; ++nt) {
            int r = wm * 32 + mt * 16 + tr, c = wn * 32 + nt * 8 + tc * 2;
            size_t o0 = (size_t)(n0 + r) * D + c, o1 = (size_t)(n0 + r + 8) * D + c;
            float2 x0 = *(const float2*)(x + o0);
            float2 x1v = *(const float2*)(x + o1);
            float2 w0, w1;
            w0.x = fmaf(g1, acc[mt][nt][0] + sBias[c],     x0.x);
            w0.y = fmaf(g1, acc[mt][nt][1] + sBias[c + 1], x0.y);
            w1.x = fmaf(g1, acc[mt][nt][2] + sBias[c],     x1v.x);
            w1.y = fmaf(g1, acc[mt][nt][3] + sBias[c + 1], x1v.y);
            *(float2*)(g_x1 + o0) = w0;
            *(float2*)(g_x1 + o1) = w1;
        }
}

// ---------------- K6: out = x1 + g2*(gelu(ln(x1)@W1+b1)@W2+b2) ----------------
__global__ __launch_bounds__(512, 1) void k_mlp(float* __restrict__ out,
                                                const float* __restrict__ b1m,
                                                const float* __restrict__ b2m) {
    extern __shared__ char sm[];
    float* sBias = (float*)(sm + OFF_BIAS);
    float* sA = (float*)(sm + OFF_A);
    float* sB = (float*)(sm + OFF_B);
    float* sC = (float*)(sm + OFF_C);
    int tid = threadIdx.x, wid = tid >> 5, lane = tid & 31;
    int wm = wid & 3, wn = wid >> 2, tr = lane >> 2, tc = lane & 3;
    int n0 = blockIdx.x * 128;
    int b = n0 >> 13;
    if (tid < 128) {
#pragma unroll
        for (int q = 0; q < 4; ++q) sBias[q * 128 + tid] = b1m[q * 128 + tid];
        sBias[512 + tid] = b2m[tid];
    }
    float s2p = 1.f + g_scal[b][3], b2s = g_scal[b][4], g2 = g_scal[b][5];

#pragma unroll
    for (int it = 0; it < 8; ++it) {
        int row = wid * 8 + it;
        const float* xp = g_x1 + (size_t)(n0 + row) * D;
        float v0 = xp[lane], v1 = xp[lane + 32], v2 = xp[lane + 64], v3 = xp[lane + 96];
        float m = warp_sum(v0 + v1 + v2 + v3) * (1.f / 128.f);
        float d0 = v0 - m, d1 = v1 - m, d2 = v2 - m, d3 = v3 - m;
        float rs = rsqrtf(warp_sum(d0*d0 + d1*d1 + d2*d2 + d3*d3) * (1.f / 128.f) + 1e-6f);
        float* ap = sA + row * STRIDE;
        ap[lane]      = to_tf32(fmaf(s2p, d0 * rs, b2s));
        ap[lane + 32] = to_tf32(fmaf(s2p, d1 * rs, b2s));
        ap[lane + 64] = to_tf32(fmaf(s2p, d2 * rs, b2s));
        ap[lane + 96] = to_tf32(fmaf(s2p, d3 * rs, b2s));
    }

    float macc[2][4][4];
    ZACC(macc);
    for (int cc = 0; cc < 4; ++cc) {
        cp_tileT(sB, g_WT[5 + cc], tid);
        __syncthreads();
        float tacc[2][4][4];
        ZACC(tacc);
        wgemm(sA, sB, tacc, wm, wn, tr, tc);
        __syncthreads();                    // done with sB (and prev sC reads)
#pragma unroll
        for (int mt = 0; mt < 2; ++mt)
#pragma unroll
            for (int nt = 0; nt < 4; ++nt) {
                int r = wm * 32 + mt * 16 + tr, c = wn * 32 + nt * 8 + tc * 2;
                sC[r * STRIDE + c]           = to_tf32(geluf_(tacc[mt][nt][0] + sBias[cc * 128 + c]));
                sC[r * STRIDE + c + 1]       = to_tf32(geluf_(tacc[mt][nt][1] + sBias[cc * 128 + c + 1]));
                sC[(r + 8) * STRIDE + c]     = to_tf32(geluf_(tacc[mt][nt][2] + sBias[cc * 128 + c]));
                sC[(r + 8) * STRIDE + c + 1] = to_tf32(geluf_(tacc[mt][nt][3] + sBias[cc * 128 + c + 1]));
            }
        cp_tileT(sB, g_WT[9 + cc], tid);
        __syncthreads();
        wgemm(sC, sB, macc, wm, wn, tr, tc);
        __syncthreads();                    // before next W1 overwrite of sB
    }

#pragma unroll
    for (int mt = 0; mt < 2; ++mt)
#pragma unroll
        for (int nt = 0; nt < 4; ++nt) {
            int r = wm * 32 + mt * 16 + tr, c = wn * 32 + nt * 8 + tc * 2;
            size_t o0 = (size_t)(n0 + r) * D + c, o1 = (size_t)(n0 + r + 8) * D + c;
            float2 x0 = *(const float2*)(g_x1 + o0);
            float2 x1v = *(const float2*)(g_x1 + o1);
            float2 w0, w1;
            w0.x = fmaf(g2, macc[mt][nt][0] + sBias[512 + c],     x0.x);
            w0.y = fmaf(g2, macc[mt][nt][1] + sBias[512 + c + 1], x0.y);
            w1.x = fmaf(g2, macc[mt][nt][2] + sBias[512 + c],     x1v.x);
            w1.y = fmaf(g2, macc[mt][nt][3] + sBias[512 + c + 1], x1v.y);
            *(float2*)(out + o0) = w0;
            *(float2*)(out + o1) = w1;
        }
}

// ---------------- launch ----------------
extern "C" void kernel_launch(void* const* d_in, const int* in_sizes, int n_in,
                              void* d_out, int out_size) {
    const float* x        = (const float*)d_in[0];
    const float* c        = (const float*)d_in[1];
    const float* cln1_sw  = (const float*)d_in[2];
    const float* cln1_sb  = (const float*)d_in[3];
    const float* cln1_bw  = (const float*)d_in[4];
    const float* cln1_bb  = (const float*)d_in[5];
    const float* gate1_w  = (const float*)d_in[6];
    const float* gate1_b  = (const float*)d_in[7];
    const float* rnn_in_w = (const float*)d_in[8];
    const float* rnn_in_b = (const float*)d_in[9];
    const float* pos_emb  = (const float*)d_in[10];
    const float* rnn_wi   = (const float*)d_in[11];
    const float* rnn_bi   = (const float*)d_in[12];
    const float* rnn_wr   = (const float*)d_in[13];
    const float* rnn_br   = (const float*)d_in[14];
    const float* rnn_a    = (const float*)d_in[15];
    const float* rnn_out_w= (const float*)d_in[16];
    const float* rnn_out_b= (const float*)d_in[17];
    const float* cln2_sw  = (const float*)d_in[18];
    const float* cln2_sb  = (const float*)d_in[19];
    const float* cln2_bw  = (const float*)d_in[20];
    const float* cln2_bb  = (const float*)d_in[21];
    const float* gate2_w  = (const float*)d_in[22];
    const float* gate2_b  = (const float*)d_in[23];
    const float* mlp_w1   = (const float*)d_in[24];
    const float* mlp_b1   = (const float*)d_in[25];
    const float* mlp_w2   = (const float*)d_in[26];
    const float* mlp_b2   = (const float*)d_in[27];
    float* out = (float*)d_out;

    cudaFuncSetAttribute(k_front, cudaFuncAttributeMaxDynamicSharedMemorySize, SMEM_SZ);
    cudaFuncSetAttribute(k_rout,  cudaFuncAttributeMaxDynamicSharedMemorySize, SMEM_SZ);
    cudaFuncSetAttribute(k_mlp,   cudaFuncAttributeMaxDynamicSharedMemorySize, SMEM_SZ);

    k_scal<<<1, 256>>>(c, cln1_sw, cln1_sb, cln1_bw, cln1_bb, gate1_w, gate1_b,
                       cln2_sw, cln2_sb, cln2_bw, cln2_bb, gate2_w, gate2_b, rnn_a);
    k_prep<<<52, 256>>>(rnn_in_w, rnn_wi, rnn_wr, rnn_out_w, mlp_w1, mlp_w2);
    k_front<<<NTOK / 128, 512, SMEM_SZ>>>(x, pos_emb, rnn_in_b, rnn_bi, rnn_br);
    k_rout<<<NTOK / 128, 512, SMEM_SZ>>>(x, rnn_out_b);
    k_mlp<<<NTOK / 128, 512, SMEM_SZ>>>(out, mlp_b1, mlp_b2);
}

// round 10
// speedup vs baseline: 3.3007x; 1.0498x over previous
#include <cuda_runtime.h>
#include <math.h>
#include <stdint.h>

#define BS   8
#define LSEQ 8192
#define D    128
#define H    128
#define NTOK (BS * LSEQ)
#define CL   128
#define NCH  (LSEQ / CL)   // 64

#define STRIDE    132                       // floats per smem tile row
#define TILE_B    (128 * STRIDE * 4)        // 67584 bytes
#define OFF_BIAS  0
#define OFF_A     4096
#define OFF_B     (OFF_A + TILE_B)
#define OFF_C     (OFF_B + TILE_B)
#define SMEM_SZ   (OFF_C + TILE_B)          // 206848

// ---------------- device scratch ----------------
__device__ __align__(16) float g_scal[BS][6];
__device__ __align__(16) float g_loga[H];          // log2(a)
__device__ __align__(16) float g_WT[13][16384];    // transposed tf32 weights [n][k]
__device__ __align__(16) float g_at[(size_t)NTOK * H];
__device__ __align__(16) float g_bt[(size_t)NTOK * H];
__device__ __align__(16) float g_x1[(size_t)NTOK * D];
__device__ __align__(16) float g_A [BS * NCH * H];
__device__ __align__(16) float g_Bf[BS * NCH * H];
__device__ __align__(16) float g_Bb[BS * NCH * H];

// ---------------- helpers ----------------
__device__ __forceinline__ float to_tf32(float x) {
    uint32_t u;
    asm("cvt.rna.tf32.f32 %0, %1;" : "=r"(u) : "f"(x));
    return __uint_as_float(u);
}
__device__ __forceinline__ float fast_ex2(float x) { float y; asm("ex2.approx.f32 %0, %1;" : "=f"(y) : "f"(x)); return y; }
__device__ __forceinline__ float fast_rcp(float x) { float y; asm("rcp.approx.f32 %0, %1;" : "=f"(y) : "f"(x)); return y; }
__device__ __forceinline__ float sigf(float v) { return fast_rcp(1.f + fast_ex2(-1.4426950408889634f * v)); }
__device__ __forceinline__ float tanh_(float x) { return 1.f - 2.f * fast_rcp(1.f + fast_ex2(2.8853900817779268f * x)); }
__device__ __forceinline__ float geluf_(float v) {
    float v3 = v * v * v;
    return 0.5f * v * (1.f + tanh_(0.7978845608028654f * (v + 0.044715f * v3)));
}
__device__ __forceinline__ float warp_sum(float v) {
    v += __shfl_xor_sync(0xffffffffu, v, 16);
    v += __shfl_xor_sync(0xffffffffu, v, 8);
    v += __shfl_xor_sync(0xffffffffu, v, 4);
    v += __shfl_xor_sync(0xffffffffu, v, 2);
    v += __shfl_xor_sync(0xffffffffu, v, 1);
    return v;
}

#define MMA168(c, a, b0, b1)                                                        \
    asm volatile("mma.sync.aligned.m16n8k8.row.col.f32.tf32.tf32.f32 "              \
                 "{%0,%1,%2,%3}, {%4,%5,%6,%7}, {%8,%9}, {%0,%1,%2,%3};"            \
                 : "+f"((c)[0]), "+f"((c)[1]), "+f"((c)[2]), "+f"((c)[3])           \
                 : "r"((a)[0]), "r"((a)[1]), "r"((a)[2]), "r"((a)[3]),              \
                   "r"(b0), "r"(b1))

#define ZACC(a) do {                                                                \
    _Pragma("unroll") for (int _m = 0; _m < 2; ++_m)                                \
    _Pragma("unroll") for (int _n = 0; _n < 4; ++_n)                                \
    _Pragma("unroll") for (int _q = 0; _q < 4; ++_q) (a)[_m][_n][_q] = 0.f;         \
} while (0)

// warp GEMM: 32x32 patch of C(128x128) += A(128x128) * B^T stored [n][k]; 16 warps
__device__ __forceinline__ void wgemm(const float* __restrict__ sA,
                                      const float* __restrict__ sB,
                                      float (&acc)[2][4][4],
                                      int wm, int wn, int tr, int tc) {
#pragma unroll 4
    for (int ks = 0; ks < 16; ++ks) {
        int k0 = ks * 8;
        uint32_t a[2][4];
#pragma unroll
        for (int mt = 0; mt < 2; ++mt) {
            const float* ap = sA + (wm * 32 + mt * 16 + tr) * STRIDE + k0 + tc;
            a[mt][0] = __float_as_uint(ap[0]);
            a[mt][1] = __float_as_uint(ap[8 * STRIDE]);
            a[mt][2] = __float_as_uint(ap[4]);
            a[mt][3] = __float_as_uint(ap[8 * STRIDE + 4]);
        }
#pragma unroll
        for (int nt = 0; nt < 4; ++nt) {
            const float* bp = sB + (wn * 32 + nt * 8 + tr) * STRIDE + k0 + tc;
            uint32_t b0 = __float_as_uint(bp[0]);
            uint32_t b1 = __float_as_uint(bp[4]);
#pragma unroll
            for (int mt = 0; mt < 2; ++mt) MMA168(acc[mt][nt], a[mt], b0, b1);
        }
    }
}

// copy a prepared 128x128 tf32 tile (contiguous) into smem with STRIDE rows
__device__ __forceinline__ void cp_tileT(float* dst, const float* __restrict__ src, int tid) {
#pragma unroll
    for (int it = 0; it < 8; ++it) {
        int idx = tid + it * 512;              // float4 index
        int row = idx >> 5, j = idx & 31;
        *(float4*)(dst + row * STRIDE + j * 4) = ((const float4*)src)[idx];
    }
}

// ---------------- K0: conditioning scalars + log2(a) ----------------
__global__ void k_scal(const float* __restrict__ c,
                       const float* sw1, const float* sb1, const float* bw1, const float* bb1,
                       const float* gw1, const float* gb1, const float* sw2, const float* sb2,
                       const float* bw2, const float* bb2, const float* gw2, const float* gb2,
                       const float* __restrict__ a) {
    int tid = threadIdx.x;
    if (tid < 48) {
        const float* ws[6] = {sw1, bw1, gw1, sw2, bw2, gw2};
        const float* bs[6] = {sb1, bb1, gb1, sb2, bb2, gb2};
        int b = tid / 6, j = tid % 6;
        float s = bs[j][0];
        const float* cp = c + b * 128;
        for (int k = 0; k < 128; ++k) s = fmaf(cp[k], ws[j][k], s);
        g_scal[b][j] = s;
    }
    int i = tid - 64;
    if (i >= 0 && i < H) g_loga[i] = log2f(a[i]);
}

// ---------------- K-prep: transposed tf32 weight tiles (52 blocks) ----------------
__global__ void k_prep(const float* __restrict__ Win, const float* __restrict__ Wi,
                       const float* __restrict__ Wr, const float* __restrict__ Wout,
                       const float* __restrict__ W1, const float* __restrict__ W2) {
    int t = blockIdx.x >> 2, quarter = blockIdx.x & 3, tid = threadIdx.x;
    for (int i = quarter * 16; i < quarter * 16 + 16; ++i) {
        int e = i * 256 + tid;
        int n = e >> 7, k = e & 127;
        float v;
        if (t == 0)      v = Win[k * 128 + n];
        else if (t == 1) v = Wi[k * 128 + n];
        else if (t == 2) v = Wr[k * 128 + n];
        else if (t == 3) v = Wout[k * 128 + n];
        else if (t == 4) v = Wout[(128 + k) * 128 + n];
        else if (t < 9)  v = W1[k * 512 + (t - 5) * 128 + n];
        else             v = W2[((t - 9) * 128 + k) * 128 + n];
        g_WT[t][n * 128 + k] = to_tf32(v);
    }
}

// ---------------- K1: x -> (at, bt) + chunk scan aggregates ----------------
__global__ __launch_bounds__(512, 1) void k_front(
    const float* __restrict__ x, const float* __restrict__ pos,
    const float* __restrict__ inb, const float* __restrict__ bi,
    const float* __restrict__ br) {
    extern __shared__ char sm[];
    float* sBias = (float*)(sm + OFF_BIAS);
    float* sA = (float*)(sm + OFF_A);
    float* sB = (float*)(sm + OFF_B);
    float* sC = (float*)(sm + OFF_C);
    int tid = threadIdx.x, wid = tid >> 5, lane = tid & 31;
    int wm = wid & 3, wn = wid >> 2, tr = lane >> 2, tc = lane & 3;
    int n0 = blockIdx.x * 128;
    int b = n0 >> 13, l0 = n0 & (LSEQ - 1);
    if (tid < 128) {
        sBias[tid] = inb[tid]; sBias[128 + tid] = bi[tid];
        sBias[256 + tid] = br[tid]; sBias[384 + tid] = g_loga[tid];
    }
    float s1p = 1.f + g_scal[b][0], b1s = g_scal[b][1];

    // conditioned double-LN -> tf32 A tile (16 warps x 8 rows)
#pragma unroll
    for (int it = 0; it < 8; ++it) {
        int row = wid * 8 + it;
        const float* xp = x + (size_t)(n0 + row) * D;
        float v0 = xp[lane], v1 = xp[lane + 32], v2 = xp[lane + 64], v3 = xp[lane + 96];
        float m = warp_sum(v0 + v1 + v2 + v3) * (1.f / 128.f);
        float d0 = v0 - m, d1 = v1 - m, d2 = v2 - m, d3 = v3 - m;
        float rs = rsqrtf(warp_sum(d0*d0 + d1*d1 + d2*d2 + d3*d3) * (1.f / 128.f) + 1e-6f);
        float h0 = fmaf(s1p, d0 * rs, b1s), h1 = fmaf(s1p, d1 * rs, b1s);
        float h2 = fmaf(s1p, d2 * rs, b1s), h3 = fmaf(s1p, d3 * rs, b1s);
        float m2 = warp_sum(h0 + h1 + h2 + h3) * (1.f / 128.f);
        float e0 = h0 - m2, e1 = h1 - m2, e2 = h2 - m2, e3 = h3 - m2;
        float rs2 = rsqrtf(warp_sum(e0*e0 + e1*e1 + e2*e2 + e3*e3) * (1.f / 128.f) + 1e-6f);
        float* ap = sA + row * STRIDE;
        ap[lane]      = to_tf32(e0 * rs2);
        ap[lane + 32] = to_tf32(e1 * rs2);
        ap[lane + 64] = to_tf32(e2 * rs2);
        ap[lane + 96] = to_tf32(e3 * rs2);
    }
    cp_tileT(sB, g_WT[0], tid);
    __syncthreads();

    float uacc[2][4][4];
    ZACC(uacc);
    wgemm(sA, sB, uacc, wm, wn, tr, tc);
    __syncthreads();                       // all warps done reading sA

    // u = gemm + bias + pos -> tf32 back into sA
#pragma unroll
    for (int mt = 0; mt < 2; ++mt)
#pragma unroll
        for (int nt = 0; nt < 4; ++nt) {
            int r = wm * 32 + mt * 16 + tr, c = wn * 32 + nt * 8 + tc * 2;
            float2 p0 = *(const float2*)(pos + (size_t)(l0 + r) * H + c);
            float2 p1 = *(const float2*)(pos + (size_t)(l0 + r + 8) * H + c);
            sA[r * STRIDE + c]           = to_tf32(uacc[mt][nt][0] + sBias[c]     + p0.x);
            sA[r * STRIDE + c + 1]       = to_tf32(uacc[mt][nt][1] + sBias[c + 1] + p0.y);
            sA[(r + 8) * STRIDE + c]     = to_tf32(uacc[mt][nt][2] + sBias[c]     + p1.x);
            sA[(r + 8) * STRIDE + c + 1] = to_tf32(uacc[mt][nt][3] + sBias[c + 1] + p1.y);
        }
    cp_tileT(sB, g_WT[1], tid);
    cp_tileT(sC, g_WT[2], tid);
    __syncthreads();

    float gacc[2][4][4];
    ZACC(gacc);
    wgemm(sA, sB, gacc, wm, wn, tr, tc);   // input gate pre-activation
#pragma unroll
    for (int mt = 0; mt < 2; ++mt)
#pragma unroll
        for (int nt = 0; nt < 4; ++nt) {
            int c = wn * 32 + nt * 8 + tc * 2;
            gacc[mt][nt][0] = sigf(gacc[mt][nt][0] + sBias[128 + c]);
            gacc[mt][nt][1] = sigf(gacc[mt][nt][1] + sBias[128 + c + 1]);
            gacc[mt][nt][2] = sigf(gacc[mt][nt][2] + sBias[128 + c]);
            gacc[mt][nt][3] = sigf(gacc[mt][nt][3] + sBias[128 + c + 1]);
        }
    float racc[2][4][4];
    ZACC(racc);
    wgemm(sA, sC, racc, wm, wn, tr, tc);   // recurrence gate pre-activation
    __syncthreads();                       // sB/sC free for at/bt staging

#pragma unroll
    for (int mt = 0; mt < 2; ++mt)
#pragma unroll
        for (int nt = 0; nt < 4; ++nt) {
            int r = wm * 32 + mt * 16 + tr, c = wn * 32 + nt * 8 + tc * 2;
            float2 u0 = *(const float2*)(sA + r * STRIDE + c);
            float2 u1 = *(const float2*)(sA + (r + 8) * STRIDE + c);
            float la0 = sBias[384 + c], la1 = sBias[384 + c + 1];
            float gr0 = sigf(racc[mt][nt][0] + sBias[256 + c]);
            float gr1 = sigf(racc[mt][nt][1] + sBias[256 + c + 1]);
            float gr2 = sigf(racc[mt][nt][2] + sBias[256 + c]);
            float gr3 = sigf(racc[mt][nt][3] + sBias[256 + c + 1]);
            float a0 = fast_ex2(8.f * gr0 * la0);
            float a1 = fast_ex2(8.f * gr1 * la1);
            float a2 = fast_ex2(8.f * gr2 * la0);
            float a3 = fast_ex2(8.f * gr3 * la1);
            float b0v = sqrtf(fmaxf(0.f, 1.f - a0 * a0)) * gacc[mt][nt][0] * u0.x;
            float b1v = sqrtf(fmaxf(0.f, 1.f - a1 * a1)) * gacc[mt][nt][1] * u0.y;
            float b2v = sqrtf(fmaxf(0.f, 1.f - a2 * a2)) * gacc[mt][nt][2] * u1.x;
            float b3v = sqrtf(fmaxf(0.f, 1.f - a3 * a3)) * gacc[mt][nt][3] * u1.y;
            size_t o0 = (size_t)(n0 + r) * H + c, o1 = (size_t)(n0 + r + 8) * H + c;
            *(float2*)(g_at + o0) = make_float2(a0, a1);
            *(float2*)(g_at + o1) = make_float2(a2, a3);
            *(float2*)(g_bt + o0) = make_float2(b0v, b1v);
            *(float2*)(g_bt + o1) = make_float2(b2v, b3v);
            // stage into smem for the chunk-local scan (fp32)
            *(float2*)(sB + r * STRIDE + c)       = make_float2(a0, a1);
            *(float2*)(sB + (r + 8) * STRIDE + c) = make_float2(a2, a3);
            *(float2*)(sC + r * STRIDE + c)       = make_float2(b0v, b1v);
            *(float2*)(sC + (r + 8) * STRIDE + c) = make_float2(b2v, b3v);
        }
    __syncthreads();

    // chunk-local scan aggregates: fwd (tid<128) || bwd (tid 128..255)
    if (tid < 128) {
        int h = tid;
        float A = 1.f, hf = 0.f;
#pragma unroll 4
        for (int t = 0; t < CL; ++t) {
            float a = sB[t * STRIDE + h], bv = sC[t * STRIDE + h];
            A *= a;
            hf = fmaf(a, hf, bv);
        }
        int o = blockIdx.x * H + h;
        g_A[o] = A; g_Bf[o] = hf;
    } else if (tid < 256) {
        int h = tid - 128;
        float hb = 0.f;
#pragma unroll 4
        for (int t = CL - 1; t >= 0; --t)
            hb = fmaf(sB[t * STRIDE + h], hb, sC[t * STRIDE + h]);
        g_Bb[blockIdx.x * H + h] = hb;
    }
}

// ---------------- K5: per-CTA carry + parallel scans + x1 = x + g1*([hf|hb]@Wout + b) ----------------
__global__ __launch_bounds__(512, 1) void k_rout(const float* __restrict__ x,
                                                 const float* __restrict__ bout) {
    extern __shared__ char sm[];
    float* sBias = (float*)(sm + OFF_BIAS);
    float* sA = (float*)(sm + OFF_A);   // weights
    float* sB = (float*)(sm + OFF_B);   // bt -> hb
    float* sC = (float*)(sm + OFF_C);   // bt -> hf
    int tid = threadIdx.x, wid = tid >> 5, lane = tid & 31;
    int wm = wid & 3, wn = wid >> 2, tr = lane >> 2, tc = lane & 3;
    int n0 = blockIdx.x * 128;
    int b = n0 >> 13;
    int bc = blockIdx.x;
    int bchunk = bc & (NCH - 1);           // chunk index within sequence
    int cbase = bc - bchunk;               // first chunk of this batch

    float cf = 0.f, cb = 0.f;
    if (tid < 128) {
        // forward carry for h=tid
        sBias[tid] = bout[tid];
        int h = tid;
        for (int i0 = 0; i0 < bchunk; i0 += 8) {
            float a[8], bf[8];
#pragma unroll
            for (int j = 0; j < 8; ++j) {
                int i = i0 + j;
                bool v = i < bchunk;
                int idx = (cbase + (v ? i : 0)) * H + h;
                a[j]  = v ? g_A[idx]  : 1.f;
                bf[j] = v ? g_Bf[idx] : 0.f;
            }
#pragma unroll
            for (int j = 0; j < 8; ++j) cf = fmaf(a[j], cf, bf[j]);
        }
    } else if (tid < 256) {
        // backward carry for h=tid-128
        int h = tid - 128;
        for (int i0 = NCH - 1; i0 > bchunk; i0 -= 8) {
            float a[8], bb_[8];
#pragma unroll
            for (int j = 0; j < 8; ++j) {
                int i = i0 - j;
                bool v = i > bchunk;
                int idx = (cbase + (v ? i : 0)) * H + h;
                a[j]   = v ? g_A[idx]  : 1.f;
                bb_[j] = v ? g_Bb[idx] : 0.f;
            }
#pragma unroll
            for (int j = 0; j < 8; ++j) cb = fmaf(a[j], cb, bb_[j]);
        }
    } else {
        // dual-stage bt into sC and sB; stage W3 into sA
        int t = tid - 256;
        const float* gb = g_bt + (size_t)n0 * H;
#pragma unroll
        for (int it = 0; it < 16; ++it) {
            int idx = t + it * 256;
            int row = idx >> 5, j4 = (idx & 31) << 2;
            float4 v = *(const float4*)(gb + (size_t)row * 128 + j4);
            *(float4*)(sC + row * STRIDE + j4) = v;
            *(float4*)(sB + row * STRIDE + j4) = v;
        }
#pragma unroll
        for (int it = 0; it < 16; ++it) {
            int idx = t + it * 256;
            int row = idx >> 5, j = idx & 31;
            *(float4*)(sA + row * STRIDE + j * 4) = ((const float4*)g_WT[3])[idx];
        }
    }
    __syncthreads();

    // parallel scans: fwd in-place on sC (tid<128), bwd in-place on sB (tid 128..255)
    if (tid < 128) {
        int h = tid;
        const float* ap = g_at + (size_t)n0 * H + h;
        float hf = cf;
        for (int t0 = 0; t0 < CL; t0 += 8) {
            float av[8];
#pragma unroll
            for (int j = 0; j < 8; ++j) av[j] = ap[(size_t)(t0 + j) * H];
#pragma unroll
            for (int j = 0; j < 8; ++j) {
                int t = t0 + j;
                hf = fmaf(av[j], hf, sC[t * STRIDE + h]);
                sC[t * STRIDE + h] = to_tf32(hf);
            }
        }
    } else if (tid < 256) {
        int h = tid - 128;
        const float* ap = g_at + (size_t)n0 * H + h;
        float hb = cb;
        for (int t0 = CL - 8; t0 >= 0; t0 -= 8) {
            float av[8];
#pragma unroll
            for (int j = 0; j < 8; ++j) av[j] = ap[(size_t)(t0 + 7 - j) * H];
#pragma unroll
            for (int j = 0; j < 8; ++j) {
                int t = t0 + 7 - j;
                hb = fmaf(av[j], hb, sB[t * STRIDE + h]);
                sB[t * STRIDE + h] = to_tf32(hb);
            }
        }
    }
    __syncthreads();

    float acc[2][4][4];
    ZACC(acc);
    wgemm(sC, sA, acc, wm, wn, tr, tc);    // hf @ Wout_lo
    __syncthreads();                       // done reading sA
    cp_tileT(sA, g_WT[4], tid);
    __syncthreads();
    wgemm(sB, sA, acc, wm, wn, tr, tc);    // hb @ Wout_hi

    float g1 = g_scal[b][2];
#pragma unroll
    for (int mt = 0; mt < 2; ++mt)
#pragma unroll
        for (int nt = 0; nt < 4; ++nt) {
            int r = wm * 32 + mt * 16 + tr, c = wn * 32 + nt * 8 + tc * 2;
            size_t o0 = (size_t)(n0 + r) * D + c, o1 = (size_t)(n0 + r + 8) * D + c;
            float2 x0 = *(const float2*)(x + o0);
            float2 x1v = *(const float2*)(x + o1);
            float2 w0, w1;
            w0.x = fmaf(g1, acc[mt][nt][0] + sBias[c],     x0.x);
            w0.y = fmaf(g1, acc[mt][nt][1] + sBias[c + 1], x0.y);
            w1.x = fmaf(g1, acc[mt][nt][2] + sBias[c],     x1v.x);
            w1.y = fmaf(g1, acc[mt][nt][3] + sBias[c + 1], x1v.y);
            *(float2*)(g_x1 + o0) = w0;
            *(float2*)(g_x1 + o1) = w1;
        }
}

// ---------------- K6: out = x1 + g2*(gelu(ln(x1)@W1+b1)@W2+b2) ----------------
__global__ __launch_bounds__(512, 1) void k_mlp(float* __restrict__ out,
                                                const float* __restrict__ b1m,
                                                const float* __restrict__ b2m) {
    extern __shared__ char sm[];
    float* sBias = (float*)(sm + OFF_BIAS);
    float* sA = (float*)(sm + OFF_A);
    float* sB = (float*)(sm + OFF_B);
    float* sC = (float*)(sm + OFF_C);
    int tid = threadIdx.x, wid = tid >> 5, lane = tid & 31;
    int wm = wid & 3, wn = wid >> 2, tr = lane >> 2, tc = lane & 3;
    int n0 = blockIdx.x * 128;
    int b = n0 >> 13;
    if (tid < 128) {
#pragma unroll
        for (int q = 0; q < 4; ++q) sBias[q * 128 + tid] = b1m[q * 128 + tid];
        sBias[512 + tid] = b2m[tid];
    }
    float s2p = 1.f + g_scal[b][3], b2s = g_scal[b][4], g2 = g_scal[b][5];

#pragma unroll
    for (int it = 0; it < 8; ++it) {
        int row = wid * 8 + it;
        const float* xp = g_x1 + (size_t)(n0 + row) * D;
        float v0 = xp[lane], v1 = xp[lane + 32], v2 = xp[lane + 64], v3 = xp[lane + 96];
        float m = warp_sum(v0 + v1 + v2 + v3) * (1.f / 128.f);
        float d0 = v0 - m, d1 = v1 - m, d2 = v2 - m, d3 = v3 - m;
        float rs = rsqrtf(warp_sum(d0*d0 + d1*d1 + d2*d2 + d3*d3) * (1.f / 128.f) + 1e-6f);
        float* ap = sA + row * STRIDE;
        ap[lane]      = to_tf32(fmaf(s2p, d0 * rs, b2s));
        ap[lane + 32] = to_tf32(fmaf(s2p, d1 * rs, b2s));
        ap[lane + 64] = to_tf32(fmaf(s2p, d2 * rs, b2s));
        ap[lane + 96] = to_tf32(fmaf(s2p, d3 * rs, b2s));
    }

    float macc[2][4][4];
    ZACC(macc);
    for (int cc = 0; cc < 4; ++cc) {
        cp_tileT(sB, g_WT[5 + cc], tid);
        __syncthreads();
        float tacc[2][4][4];
        ZACC(tacc);
        wgemm(sA, sB, tacc, wm, wn, tr, tc);
        __syncthreads();                    // done with sB (and prev sC reads)
#pragma unroll
        for (int mt = 0; mt < 2; ++mt)
#pragma unroll
            for (int nt = 0; nt < 4; ++nt) {
                int r = wm * 32 + mt * 16 + tr, c = wn * 32 + nt * 8 + tc * 2;
                sC[r * STRIDE + c]           = to_tf32(geluf_(tacc[mt][nt][0] + sBias[cc * 128 + c]));
                sC[r * STRIDE + c + 1]       = to_tf32(geluf_(tacc[mt][nt][1] + sBias[cc * 128 + c + 1]));
                sC[(r + 8) * STRIDE + c]     = to_tf32(geluf_(tacc[mt][nt][2] + sBias[cc * 128 + c]));
                sC[(r + 8) * STRIDE + c + 1] = to_tf32(geluf_(tacc[mt][nt][3] + sBias[cc * 128 + c + 1]));
            }
        cp_tileT(sB, g_WT[9 + cc], tid);
        __syncthreads();
        wgemm(sC, sB, macc, wm, wn, tr, tc);
        __syncthreads();                    // before next W1 overwrite of sB
    }

#pragma unroll
    for (int mt = 0; mt < 2; ++mt)
#pragma unroll
        for (int nt = 0; nt < 4; ++nt) {
            int r = wm * 32 + mt * 16 + tr, c = wn * 32 + nt * 8 + tc * 2;
            size_t o0 = (size_t)(n0 + r) * D + c, o1 = (size_t)(n0 + r + 8) * D + c;
            float2 x0 = *(const float2*)(g_x1 + o0);
            float2 x1v = *(const float2*)(g_x1 + o1);
            float2 w0, w1;
            w0.x = fmaf(g2, macc[mt][nt][0] + sBias[512 + c],     x0.x);
            w0.y = fmaf(g2, macc[mt][nt][1] + sBias[512 + c + 1], x0.y);
            w1.x = fmaf(g2, macc[mt][nt][2] + sBias[512 + c],     x1v.x);
            w1.y = fmaf(g2, macc[mt][nt][3] + sBias[512 + c + 1], x1v.y);
            *(float2*)(out + o0) = w0;
            *(float2*)(out + o1) = w1;
        }
}

// ---------------- launch ----------------
extern "C" void kernel_launch(void* const* d_in, const int* in_sizes, int n_in,
                              void* d_out, int out_size) {
    const float* x        = (const float*)d_in[0];
    const float* c        = (const float*)d_in[1];
    const float* cln1_sw  = (const float*)d_in[2];
    const float* cln1_sb  = (const float*)d_in[3];
    const float* cln1_bw  = (const float*)d_in[4];
    const float* cln1_bb  = (const float*)d_in[5];
    const float* gate1_w  = (const float*)d_in[6];
    const float* gate1_b  = (const float*)d_in[7];
    const float* rnn_in_w = (const float*)d_in[8];
    const float* rnn_in_b = (const float*)d_in[9];
    const float* pos_emb  = (const float*)d_in[10];
    const float* rnn_wi   = (const float*)d_in[11];
    const float* rnn_bi   = (const float*)d_in[12];
    const float* rnn_wr   = (const float*)d_in[13];
    const float* rnn_br   = (const float*)d_in[14];
    const float* rnn_a    = (const float*)d_in[15];
    const float* rnn_out_w= (const float*)d_in[16];
    const float* rnn_out_b= (const float*)d_in[17];
    const float* cln2_sw  = (const float*)d_in[18];
    const float* cln2_sb  = (const float*)d_in[19];
    const float* cln2_bw  = (const float*)d_in[20];
    const float* cln2_bb  = (const float*)d_in[21];
    const float* gate2_w  = (const float*)d_in[22];
    const float* gate2_b  = (const float*)d_in[23];
    const float* mlp_w1   = (const float*)d_in[24];
    const float* mlp_b1   = (const float*)d_in[25];
    const float* mlp_w2   = (const float*)d_in[26];
    const float* mlp_b2   = (const float*)d_in[27];
    float* out = (float*)d_out;

    cudaFuncSetAttribute(k_front, cudaFuncAttributeMaxDynamicSharedMemorySize, SMEM_SZ);
    cudaFuncSetAttribute(k_rout,  cudaFuncAttributeMaxDynamicSharedMemorySize, SMEM_SZ);
    cudaFuncSetAttribute(k_mlp,   cudaFuncAttributeMaxDynamicSharedMemorySize, SMEM_SZ);

    k_scal<<<1, 256>>>(c, cln1_sw, cln1_sb, cln1_bw, cln1_bb, gate1_w, gate1_b,
                       cln2_sw, cln2_sb, cln2_bw, cln2_bb, gate2_w, gate2_b, rnn_a);
    k_prep<<<52, 256>>>(rnn_in_w, rnn_wi, rnn_wr, rnn_out_w, mlp_w1, mlp_w2);
    k_front<<<NTOK / 128, 512, SMEM_SZ>>>(x, pos_emb, rnn_in_b, rnn_bi, rnn_br);
    k_rout<<<NTOK / 128, 512, SMEM_SZ>>>(x, rnn_out_b);
    k_mlp<<<NTOK / 128, 512, SMEM_SZ>>>(out, mlp_b1, mlp_b2);
}